// round 8
// baseline (speedup 1.0000x reference)
#include <cuda_runtime.h>
#include <cuda_bf16.h>
#include <math.h>
#include <stdint.h>
#include <stddef.h>

#define SS 512
#define DD 1024
#define NNH 4096
#define VV 32000
#define MROWS 1024
#define MMDD (MROWS * DD)
#define EPSLN 1e-5f
#define GRU_CTAS 128

// ---------------- device scratch ----------------
__device__ float  g_x[MROWS * DD];
__device__ float  g_y[MROWS * DD];
__device__ float  g_gi[MROWS * 3 * DD];
__device__ float  g_hid[MROWS * NNH];
__device__ float  g_psum[4 * MROWS * DD];
__device__ float  g_h[2][2 * DD];
__device__ double g_part[10 * 512];
__device__ float  g_scale[10];
__device__ float  g_scaleinv[10];
__device__ unsigned g_bar_cnt;
__device__ unsigned g_bar_phase;
__device__ unsigned g_ack;

// bf16 buffers (in-proj only)
__device__ __nv_bfloat16 g_wihhi[3 * DD * DD];
__device__ __nv_bfloat16 g_wihlo[3 * DD * DD];
__device__ __nv_bfloat16 g_xhi[MROWS * DD], g_xlo[MROWS * DD];

// int8 buffers
__device__ __align__(256) char4 g_w8syn[4 * NNH * DD / 4];
__device__ __align__(256) char4 g_w8out[4 * NNH * DD / 4];
__device__ __align__(256) char4 g_w8head[VV * DD / 4];
__device__ __align__(256) char4 g_xa8[MROWS * DD / 4],  g_xb8[MROWS * DD / 4];
__device__ __align__(256) char4 g_ha8[MROWS * NNH / 4], g_hb8[MROWS * NNH / 4];
__device__ __align__(256) char4 g_ya8[MROWS * DD / 4],  g_yb8[MROWS * DD / 4];
__device__ float g_rsx[MROWS], g_rsh[MROWS], g_rsy[MROWS];

// ---------------- asm helpers ----------------
#define CP16(dst, src) asm volatile("cp.async.cg.shared.global [%0], [%1], 16;" :: "r"(dst), "l"(src))
#define CPCOMMIT() asm volatile("cp.async.commit_group;")
#define CPWAIT1()  asm volatile("cp.async.wait_group 1;")
#define LDSM4(r, addr) asm volatile( \
    "ldmatrix.sync.aligned.m8n8.x4.shared.b16 {%0,%1,%2,%3}, [%4];" \
    : "=r"((r)[0]), "=r"((r)[1]), "=r"((r)[2]), "=r"((r)[3]) : "r"(addr))
#define MMA16816(d, a, b0, b1) asm volatile( \
    "mma.sync.aligned.m16n8k16.row.col.f32.bf16.bf16.f32 " \
    "{%0,%1,%2,%3},{%4,%5,%6,%7},{%8,%9},{%0,%1,%2,%3};" \
    : "+f"((d)[0]), "+f"((d)[1]), "+f"((d)[2]), "+f"((d)[3]) \
    : "r"((a)[0]), "r"((a)[1]), "r"((a)[2]), "r"((a)[3]), "r"(b0), "r"(b1))
#define IMMA16832(d, a, b0, b1) asm volatile( \
    "mma.sync.aligned.m16n8k32.row.col.s32.s8.s8.s32 " \
    "{%0,%1,%2,%3},{%4,%5,%6,%7},{%8,%9},{%0,%1,%2,%3};" \
    : "+r"((d)[0]), "+r"((d)[1]), "+r"((d)[2]), "+r"((d)[3]) \
    : "r"((a)[0]), "r"((a)[1]), "r"((a)[2]), "r"((a)[3]), "r"(b0), "r"(b1))

__device__ __forceinline__ unsigned short bf16bits(float x) {
    return __bfloat16_as_ushort(__float2bfloat16(x));
}
__device__ __forceinline__ unsigned long long pk2(float x, float y) {
    unsigned long long r;
    asm("mov.b64 %0, {%1, %2};" : "=l"(r) : "f"(x), "f"(y));
    return r;
}
__device__ __forceinline__ void ffma2(unsigned long long& d, unsigned long long a, unsigned long long b) {
    asm("fma.rn.f32x2 %0, %1, %2, %0;" : "+l"(d) : "l"(a), "l"(b));
}
__device__ __forceinline__ float2 unpk(unsigned long long v) {
    float2 f;
    asm("mov.b64 {%0, %1}, %2;" : "=f"(f.x), "=f"(f.y) : "l"(v));
    return f;
}
// two-level int8 split: x*inv = 128*a + b  (|a|<=127, |b|<=64)
__device__ __forceinline__ void qsplit(float v, float inv, signed char& a, signed char& b) {
    float t = v * inv;
    float af = rintf(t * (1.f / 128.f));
    float bf = rintf(t - 128.f * af);
    a = (signed char)(int)af;
    b = (signed char)(int)bf;
}

// ---------------- abs-mean scale ----------------
__global__ __launch_bounds__(256, 2) void absmean_part(const float4* __restrict__ src, long n4, int slot) {
    __shared__ double sred[256];
    double a[8];
#pragma unroll
    for (int c = 0; c < 8; c++) a[c] = 0.0;
    const long stride = (long)gridDim.x * 256;
    long i = (long)blockIdx.x * 256 + threadIdx.x;
    for (; i + 7 * stride < n4; i += 8 * stride) {
        float4 v[8];
#pragma unroll
        for (int c = 0; c < 8; c++) v[c] = src[i + c * stride];
#pragma unroll
        for (int c = 0; c < 8; c++)
            a[c] += (double)(fabsf(v[c].x) + fabsf(v[c].y)) + (double)(fabsf(v[c].z) + fabsf(v[c].w));
    }
    for (; i < n4; i += stride) {
        float4 v = src[i];
        a[0] += (double)(fabsf(v.x) + fabsf(v.y)) + (double)(fabsf(v.z) + fabsf(v.w));
    }
    sred[threadIdx.x] = ((a[0] + a[1]) + (a[2] + a[3])) + ((a[4] + a[5]) + (a[6] + a[7]));
    __syncthreads();
#pragma unroll
    for (int o = 128; o > 0; o >>= 1) {
        if ((int)threadIdx.x < o) sred[threadIdx.x] += sred[threadIdx.x + o];
        __syncthreads();
    }
    if (threadIdx.x == 0) g_part[slot * 512 + blockIdx.x] = sred[0];
}

__global__ void absmean_final(int base) {
    __shared__ double sred[256];
    int slot = base + blockIdx.x, t = threadIdx.x;
    sred[t] = g_part[slot * 512 + t] + g_part[slot * 512 + 256 + t];
    __syncthreads();
#pragma unroll
    for (int o = 128; o > 0; o >>= 1) {
        if (t < o) sred[t] += sred[t + o];
        __syncthreads();
    }
    if (t == 0) {
        double cnt = (slot < 2) ? (double)VV * DD : (double)NNH * DD;
        double s = sred[0] / cnt + 1e-8;
        g_scale[slot]    = (float)s;
        g_scaleinv[slot] = (float)(1.0 / s);
    }
}

// ---------------- weight quantization ----------------
__global__ void tern_quant8(const float4* __restrict__ w, char4* __restrict__ q,
                            int slot, int n4) {
    int i = blockIdx.x * 256 + threadIdx.x;
    if (i >= n4) return;
    float inv = g_scaleinv[slot];
    float4 v = w[i];
    char4 o;
    o.x = (signed char)(int)rintf(fminf(fmaxf(v.x * inv, -1.f), 1.f));
    o.y = (signed char)(int)rintf(fminf(fmaxf(v.y * inv, -1.f), 1.f));
    o.z = (signed char)(int)rintf(fminf(fmaxf(v.z * inv, -1.f), 1.f));
    o.w = (signed char)(int)rintf(fminf(fmaxf(v.w * inv, -1.f), 1.f));
    q[i] = o;
}

__global__ void hilo_quant(const float4* __restrict__ w, ushort4* __restrict__ hi,
                           ushort4* __restrict__ lo, int n4) {
    int i = blockIdx.x * 256 + threadIdx.x;
    if (i >= n4) return;
    float4 v = w[i];
    ushort4 h, l;
    __nv_bfloat16 hb;
    hb = __float2bfloat16(v.x); h.x = __bfloat16_as_ushort(hb); l.x = bf16bits(v.x - __bfloat162float(hb));
    hb = __float2bfloat16(v.y); h.y = __bfloat16_as_ushort(hb); l.y = bf16bits(v.y - __bfloat162float(hb));
    hb = __float2bfloat16(v.z); h.z = __bfloat16_as_ushort(hb); l.z = bf16bits(v.z - __bfloat162float(hb));
    hb = __float2bfloat16(v.w); h.w = __bfloat16_as_ushort(hb); l.w = bf16bits(v.w - __bfloat162float(hb));
    hi[i] = h; lo[i] = l;
}

// ---------------- embedding ----------------
__global__ void embed_kernel(const int* __restrict__ ids, const float* __restrict__ emb,
                             const float* __restrict__ pos, float* __restrict__ x,
                             __nv_bfloat16* __restrict__ xhi, __nv_bfloat16* __restrict__ xlo) {
    int i = blockIdx.x * 256 + threadIdx.x;
    int d = i & (DD - 1);
    int s = (i >> 10) & (SS - 1);
    int b = i >> 19;
    int tok = ids[b * SS + s];
    float w = emb[(size_t)tok * DD + d];
    float tn = g_scale[0] * rintf(fminf(fmaxf(w * g_scaleinv[0], -1.f), 1.f));
    float v = tn + pos[s * DD + d];
    x[i] = v;
    __nv_bfloat16 h = __float2bfloat16(v);
    xhi[i] = h;
    xlo[i] = __float2bfloat16(v - __bfloat162float(h));
}

// ---------------- activation quantization (row = 1024) ----------------
__global__ void x_quant8(const float4* __restrict__ x, char4* __restrict__ a8,
                         char4* __restrict__ b8, float* __restrict__ rs) {
    __shared__ float sm[256];
    const int row = blockIdx.x, t = threadIdx.x;
    float4 v = x[row * 256 + t];
    sm[t] = fmaxf(fmaxf(fabsf(v.x), fabsf(v.y)), fmaxf(fabsf(v.z), fabsf(v.w)));
    __syncthreads();
#pragma unroll
    for (int o = 128; o > 0; o >>= 1) { if (t < o) sm[t] = fmaxf(sm[t], sm[t + o]); __syncthreads(); }
    float mx = fmaxf(sm[0], 1e-30f);
    float inv = 16256.f / mx;
    if (t == 0) rs[row] = mx * (1.f / 16256.f);
    char4 a, b;
    qsplit(v.x, inv, a.x, b.x);
    qsplit(v.y, inv, a.y, b.y);
    qsplit(v.z, inv, a.z, b.z);
    qsplit(v.w, inv, a.w, b.w);
    a8[row * 256 + t] = a;
    b8[row * 256 + t] = b;
}

// ---------------- hidden quantization (row = 4096) ----------------
__global__ void hid_quant8(const float4* __restrict__ x, char4* __restrict__ a8,
                           char4* __restrict__ b8, float* __restrict__ rs) {
    __shared__ float sm[256];
    const int row = blockIdx.x, t = threadIdx.x;
    float4 v[4];
    float m = 0.f;
#pragma unroll
    for (int i = 0; i < 4; i++) {
        v[i] = x[row * 1024 + t + 256 * i];
        m = fmaxf(m, fmaxf(fmaxf(fabsf(v[i].x), fabsf(v[i].y)), fmaxf(fabsf(v[i].z), fabsf(v[i].w))));
    }
    sm[t] = m;
    __syncthreads();
#pragma unroll
    for (int o = 128; o > 0; o >>= 1) { if (t < o) sm[t] = fmaxf(sm[t], sm[t + o]); __syncthreads(); }
    float mx = fmaxf(sm[0], 1e-30f);
    float inv = 16256.f / mx;
    if (t == 0) rs[row] = mx * (1.f / 16256.f);
#pragma unroll
    for (int i = 0; i < 4; i++) {
        char4 a, b;
        qsplit(v[i].x, inv, a.x, b.x);
        qsplit(v[i].y, inv, a.y, b.y);
        qsplit(v[i].z, inv, a.z, b.z);
        qsplit(v[i].w, inv, a.w, b.w);
        a8[row * 1024 + t + 256 * i] = a;
        b8[row * 1024 + t + 256 * i] = b;
    }
}

// ---------------- INT8 tensor-core GEMM NT (dual-pass) ----------------
// C[m,n] = rs[m]*wscale*( 128*(Aa.W) + (Ab.W) ) [+ bias] [relu]
// Tile 128x128, K-stage 64 int8, 256 threads, double buffered.
#define IG_MAT_BYTES 10240      // 128 rows x 80B
#define IG_STAGE_BYTES 30720
#define IG_SMEM (2 * IG_STAGE_BYTES)

template<bool RELU>
__global__ __launch_bounds__(256) void igemm(
    const char* __restrict__ Aa, const char* __restrict__ Ab,
    const char* __restrict__ B8, const float* __restrict__ rs,
    float* __restrict__ C, const float* __restrict__ bias,
    int M, int N, int Kld, int kLen, int slot)
{
    extern __shared__ __align__(16) char smc[];
    const int t = threadIdx.x, lane = t & 31, w = t >> 5;
    const int warpM = (w >> 1) << 5;
    const int warpN = (w & 1) << 6;
    const int bm = blockIdx.y << 7, bn = blockIdx.x << 7;
    const int kOff = blockIdx.z * kLen;
    if (gridDim.z > 1) C += (size_t)blockIdx.z * ((size_t)M * N);

    const char* gAa = Aa + (size_t)(bm + (t >> 1)) * Kld + kOff + (t & 1) * 32;
    const char* gAb = Ab + (size_t)(bm + (t >> 1)) * Kld + kOff + (t & 1) * 32;
    const char* gB  = B8 + (size_t)(bn + (t >> 1)) * Kld + kOff + (t & 1) * 32;
    const unsigned us = (unsigned)__cvta_generic_to_shared(smc);
    const unsigned wo = (unsigned)((t >> 1) * 80 + (t & 1) * 32);

    int accA[2][8][4], accB[2][8][4];
#pragma unroll
    for (int i = 0; i < 2; i++)
#pragma unroll
        for (int j = 0; j < 8; j++)
#pragma unroll
            for (int p = 0; p < 4; p++) { accA[i][j][p] = 0; accB[i][j][p] = 0; }

    const int NS = kLen >> 6;

#define IG_LOAD(s) do { \
    unsigned _b = us + (unsigned)((s) & 1) * IG_STAGE_BYTES; \
    int _k = (s) << 6; \
    CP16(_b + wo,                      gAa + _k); \
    CP16(_b + wo + 16,                 gAa + _k + 16); \
    CP16(_b + IG_MAT_BYTES + wo,       gAb + _k); \
    CP16(_b + IG_MAT_BYTES + wo + 16,  gAb + _k + 16); \
    CP16(_b + 2 * IG_MAT_BYTES + wo,      gB + _k); \
    CP16(_b + 2 * IG_MAT_BYTES + wo + 16, gB + _k + 16); \
    CPCOMMIT(); \
} while (0)

    IG_LOAD(0);
    if (NS > 1) IG_LOAD(1); else CPCOMMIT();

    for (int s = 0; s < NS; s++) {
        CPWAIT1();
        __syncthreads();
        unsigned base = us + (unsigned)(s & 1) * IG_STAGE_BYTES;
#pragma unroll
        for (int kk = 0; kk < 32; kk += 16) {   // b16 units; 16 b16 = 32 int8 = one k32 mma
            uint32_t aa[2][4], ab[2][4], bb[4][4];
#pragma unroll
            for (int mt = 0; mt < 2; mt++) {
                unsigned ra = base + (unsigned)((warpM + (mt << 4) + (lane & 15)) * 80)
                            + (unsigned)((kk + ((lane >> 4) << 3)) << 1);
                LDSM4(aa[mt], ra);
                LDSM4(ab[mt], ra + IG_MAT_BYTES);
            }
#pragma unroll
            for (int bj = 0; bj < 4; bj++) {
                unsigned rb = base + 2 * IG_MAT_BYTES
                            + (unsigned)((warpN + (bj << 4) + ((lane >> 4) << 3) + (lane & 7)) * 80)
                            + (unsigned)((kk + (((lane >> 3) & 1) << 3)) << 1);
                LDSM4(bb[bj], rb);
            }
#pragma unroll
            for (int mt = 0; mt < 2; mt++)
#pragma unroll
                for (int nt = 0; nt < 8; nt++) {
                    uint32_t b0 = bb[nt >> 1][(nt & 1) << 1];
                    uint32_t b1 = bb[nt >> 1][((nt & 1) << 1) + 1];
                    IMMA16832(accA[mt][nt], aa[mt], b0, b1);
                    IMMA16832(accB[mt][nt], ab[mt], b0, b1);
                }
        }
        __syncthreads();
        if (s + 2 < NS) IG_LOAD(s + 2); else CPCOMMIT();
    }
#undef IG_LOAD

    const float ws = g_scale[slot];
#pragma unroll
    for (int mt = 0; mt < 2; mt++) {
        int r0 = bm + warpM + (mt << 4) + (lane >> 2);
        float rw0 = rs[r0] * ws;
        float rw1 = rs[r0 + 8] * ws;
#pragma unroll
        for (int nt = 0; nt < 8; nt++) {
            int col = bn + warpN + (nt << 3) + ((lane & 3) << 1);
            float bb0 = bias ? bias[col] : 0.f;
            float bb1 = bias ? bias[col + 1] : 0.f;
#pragma unroll
            for (int half = 0; half < 2; half++) {
                int r = r0 + (half << 3);
                float rw = half ? rw1 : rw0;
                float v0 = (float)(accA[mt][nt][half * 2 + 0] * 128 + accB[mt][nt][half * 2 + 0]) * rw + bb0;
                float v1 = (float)(accA[mt][nt][half * 2 + 1] * 128 + accB[mt][nt][half * 2 + 1]) * rw + bb1;
                if (RELU) { v0 = fmaxf(v0, 0.f); v1 = fmaxf(v1, 0.f); }
                C[(size_t)r * N + col]     = v0;
                C[(size_t)r * N + col + 1] = v1;
            }
        }
    }
}

// ---------------- legacy bf16 GEMM (in-proj only, hi/lo x hi/lo) ----------------
__global__ __launch_bounds__(256) void bgemm_hl(
    const __nv_bfloat16* __restrict__ Ahi, const __nv_bfloat16* __restrict__ Alo,
    const __nv_bfloat16* __restrict__ Bhi, const __nv_bfloat16* __restrict__ Blo,
    float* __restrict__ C, const float* __restrict__ bias,
    int M, int N, int Kld, int kLen)
{
    constexpr int SZ = 128 * 40;
    extern __shared__ __align__(16) __nv_bfloat16 smb[];
    __nv_bfloat16* sAhi = smb;
    __nv_bfloat16* sAlo = smb + 2 * SZ;
    __nv_bfloat16* sBhi = smb + 4 * SZ;
    __nv_bfloat16* sBlo = smb + 6 * SZ;

    const int t = threadIdx.x;
    const int lane = t & 31;
    const int w = t >> 5;
    const int warpM = (w >> 1) << 5;
    const int warpN = (w & 1) << 6;
    const int bm = blockIdx.y << 7, bn = blockIdx.x << 7;

    const __nv_bfloat16* gAhi = Ahi + (size_t)bm * Kld;
    const __nv_bfloat16* gAlo = Alo + (size_t)bm * Kld;
    const __nv_bfloat16* gBhi = Bhi + (size_t)bn * Kld;
    const __nv_bfloat16* gBlo = Blo + (size_t)bn * Kld;

    const unsigned uAhi = (unsigned)__cvta_generic_to_shared(sAhi);
    const unsigned uAlo = (unsigned)__cvta_generic_to_shared(sAlo);
    const unsigned uBhi = (unsigned)__cvta_generic_to_shared(sBhi);
    const unsigned uBlo = (unsigned)__cvta_generic_to_shared(sBlo);

    const int lrow = t >> 2;
    const int lcol = (t & 3) << 3;

    float acc[2][8][4];
#pragma unroll
    for (int i = 0; i < 2; i++)
#pragma unroll
        for (int j = 0; j < 8; j++)
#pragma unroll
            for (int p = 0; p < 4; p++) acc[i][j][p] = 0.f;

    const int NS = kLen >> 5;
    {
#pragma unroll
        for (int h = 0; h < 2; h++) {
            int row = lrow + (h << 6);
            size_t go = (size_t)row * Kld + lcol;
            unsigned so = ((unsigned)(row * 40 + lcol) << 1);
            CP16(uAhi + so, gAhi + go);
            CP16(uAlo + so, gAlo + go);
            CP16(uBhi + so, gBhi + go);
            CP16(uBlo + so, gBlo + go);
        }
        CPCOMMIT();
    }

    for (int s = 0; s < NS; s++) {
        if (s + 1 < NS) {
            int k0 = (s + 1) << 5, buf = (s + 1) & 1;
#pragma unroll
            for (int h = 0; h < 2; h++) {
                int row = lrow + (h << 6);
                size_t go = (size_t)row * Kld + k0 + lcol;
                unsigned so = ((unsigned)(row * 40 + lcol) << 1) + (unsigned)buf * (SZ << 1);
                CP16(uAhi + so, gAhi + go);
                CP16(uAlo + so, gAlo + go);
                CP16(uBhi + so, gBhi + go);
                CP16(uBlo + so, gBlo + go);
            }
        }
        CPCOMMIT();
        CPWAIT1();
        __syncthreads();

        unsigned bufOff = (unsigned)(s & 1) * (SZ << 1);
#pragma unroll
        for (int kk = 0; kk < 32; kk += 16) {
            uint32_t ah[2][4], al[2][4], bh[4][4], bl[4][4];
#pragma unroll
            for (int mt = 0; mt < 2; mt++) {
                unsigned ra = ((unsigned)((warpM + (mt << 4) + (lane & 15)) * 40 + kk + ((lane >> 4) << 3)) << 1) + bufOff;
                LDSM4(ah[mt], uAhi + ra);
                LDSM4(al[mt], uAlo + ra);
            }
#pragma unroll
            for (int bj = 0; bj < 4; bj++) {
                unsigned rb = ((unsigned)((warpN + (bj << 4) + ((lane >> 4) << 3) + (lane & 7)) * 40 + kk + (((lane >> 3) & 1) << 3)) << 1) + bufOff;
                LDSM4(bh[bj], uBhi + rb);
                LDSM4(bl[bj], uBlo + rb);
            }
#pragma unroll
            for (int mt = 0; mt < 2; mt++)
#pragma unroll
                for (int nt = 0; nt < 8; nt++) {
                    uint32_t b0 = bh[nt >> 1][(nt & 1) << 1];
                    uint32_t b1 = bh[nt >> 1][((nt & 1) << 1) + 1];
                    MMA16816(acc[mt][nt], ah[mt], b0, b1);
                    MMA16816(acc[mt][nt], al[mt], b0, b1);
                    uint32_t c0 = bl[nt >> 1][(nt & 1) << 1];
                    uint32_t c1 = bl[nt >> 1][((nt & 1) << 1) + 1];
                    MMA16816(acc[mt][nt], ah[mt], c0, c1);
                }
        }
        __syncthreads();
    }

#pragma unroll
    for (int mt = 0; mt < 2; mt++)
#pragma unroll
        for (int nt = 0; nt < 8; nt++) {
            int row = bm + warpM + (mt << 4) + (lane >> 2);
            int col = bn + warpN + (nt << 3) + ((lane & 3) << 1);
#pragma unroll
            for (int half = 0; half < 2; half++) {
                int r = row + half * 8;
                float v0 = acc[mt][nt][half * 2 + 0] + bias[col];
                float v1 = acc[mt][nt][half * 2 + 1] + bias[col + 1];
                C[(size_t)r * N + col]     = v0;
                C[(size_t)r * N + col + 1] = v1;
            }
        }
}

// ---------------- fused split-K reduce + residual + LayerNorm + int8 quant ----------------
__global__ void ln_red(const float* __restrict__ bias, float* __restrict__ x,
                       char4* __restrict__ a8, char4* __restrict__ b8, float* __restrict__ rsv,
                       const float* __restrict__ gamma, const float* __restrict__ beta)
{
    __shared__ float sred[256];
    const int row = blockIdx.x, t = threadIdx.x;
    const size_t off = (size_t)row * DD;
    float4 p0 = ((const float4*)(g_psum + off))[t];
    float4 p1 = ((const float4*)(g_psum + MMDD + off))[t];
    float4 p2 = ((const float4*)(g_psum + 2 * MMDD + off))[t];
    float4 p3 = ((const float4*)(g_psum + 3 * MMDD + off))[t];
    float4 bb = ((const float4*)bias)[t];
    float4 rr = ((const float4*)(x + off))[t];
    float4 v;
    v.x = ((p0.x + p1.x) + (p2.x + p3.x)) + bb.x + rr.x;
    v.y = ((p0.y + p1.y) + (p2.y + p3.y)) + bb.y + rr.y;
    v.z = ((p0.z + p1.z) + (p2.z + p3.z)) + bb.z + rr.z;
    v.w = ((p0.w + p1.w) + (p2.w + p3.w)) + bb.w + rr.w;

    sred[t] = v.x + v.y + v.z + v.w;
    __syncthreads();
#pragma unroll
    for (int o = 128; o > 0; o >>= 1) { if (t < o) sred[t] += sred[t + o]; __syncthreads(); }
    float mean = sred[0] * (1.f / 1024.f);
    __syncthreads();
    float dx = v.x - mean, dy = v.y - mean, dz = v.z - mean, dw = v.w - mean;
    sred[t] = dx * dx + dy * dy + dz * dz + dw * dw;
    __syncthreads();
#pragma unroll
    for (int o = 128; o > 0; o >>= 1) { if (t < o) sred[t] += sred[t + o]; __syncthreads(); }
    float rstd = rsqrtf(sred[0] * (1.f / 1024.f) + EPSLN);
    float4 g = ((const float4*)gamma)[t];
    float4 b = ((const float4*)beta)[t];
    float4 o4;
    o4.x = dx * rstd * g.x + b.x;
    o4.y = dy * rstd * g.y + b.y;
    o4.z = dz * rstd * g.z + b.z;
    o4.w = dw * rstd * g.w + b.w;
    ((float4*)(x + off))[t] = o4;
    __syncthreads();
    sred[t] = fmaxf(fmaxf(fabsf(o4.x), fabsf(o4.y)), fmaxf(fabsf(o4.z), fabsf(o4.w)));
    __syncthreads();
#pragma unroll
    for (int o = 128; o > 0; o >>= 1) { if (t < o) sred[t] = fmaxf(sred[t], sred[t + o]); __syncthreads(); }
    float mx = fmaxf(sred[0], 1e-30f);
    float inv = 16256.f / mx;
    if (t == 0) rsv[row] = mx * (1.f / 16256.f);
    char4 qa, qb;
    qsplit(o4.x, inv, qa.x, qb.x);
    qsplit(o4.y, inv, qa.y, qb.y);
    qsplit(o4.z, inv, qa.z, qb.z);
    qsplit(o4.w, inv, qa.w, qb.w);
    a8[row * 256 + t] = qa;
    b8[row * 256 + t] = qb;
}

// ---------------- plain LayerNorm + int8 quant ----------------
__global__ void ln_kernel(const float* __restrict__ in, float* __restrict__ out,
                          char4* __restrict__ a8, char4* __restrict__ b8, float* __restrict__ rsv,
                          const float* __restrict__ gamma, const float* __restrict__ beta)
{
    __shared__ float sred[256];
    const int row = blockIdx.x, t = threadIdx.x;
    const float4 v = ((const float4*)(in + (size_t)row * DD))[t];
    sred[t] = v.x + v.y + v.z + v.w;
    __syncthreads();
#pragma unroll
    for (int o = 128; o > 0; o >>= 1) { if (t < o) sred[t] += sred[t + o]; __syncthreads(); }
    float mean = sred[0] * (1.f / 1024.f);
    __syncthreads();
    float dx = v.x - mean, dy = v.y - mean, dz = v.z - mean, dw = v.w - mean;
    sred[t] = dx * dx + dy * dy + dz * dz + dw * dw;
    __syncthreads();
#pragma unroll
    for (int o = 128; o > 0; o >>= 1) { if (t < o) sred[t] += sred[t + o]; __syncthreads(); }
    float rstd = rsqrtf(sred[0] * (1.f / 1024.f) + EPSLN);
    float4 g = ((const float4*)gamma)[t];
    float4 b = ((const float4*)beta)[t];
    float4 o4;
    o4.x = dx * rstd * g.x + b.x;
    o4.y = dy * rstd * g.y + b.y;
    o4.z = dz * rstd * g.z + b.z;
    o4.w = dw * rstd * g.w + b.w;
    ((float4*)(out + (size_t)row * DD))[t] = o4;
    __syncthreads();
    sred[t] = fmaxf(fmaxf(fabsf(o4.x), fabsf(o4.y)), fmaxf(fabsf(o4.z), fabsf(o4.w)));
    __syncthreads();
#pragma unroll
    for (int o = 128; o > 0; o >>= 1) { if (t < o) sred[t] = fmaxf(sred[t], sred[t + o]); __syncthreads(); }
    float mx = fmaxf(sred[0], 1e-30f);
    float inv = 16256.f / mx;
    if (t == 0) rsv[row] = mx * (1.f / 16256.f);
    char4 qa, qb;
    qsplit(o4.x, inv, qa.x, qb.x);
    qsplit(o4.y, inv, qa.y, qb.y);
    qsplit(o4.z, inv, qa.z, qb.z);
    qsplit(o4.w, inv, qa.w, qb.w);
    a8[row * 256 + t] = qa;
    b8[row * 256 + t] = qb;
}

// ---------------- grid barrier ----------------
__device__ __forceinline__ void gbar(unsigned k) {
    __syncthreads();
    if (threadIdx.x == 0) {
        __threadfence();
        unsigned tick = atomicAdd(&g_bar_cnt, 1u);
        if (tick == GRU_CTAS - 1) {
            g_bar_cnt = 0;
            __threadfence();
            atomicExch(&g_bar_phase, k);
        } else {
            while (*((volatile unsigned*)&g_bar_phase) < k) { }
            __threadfence();
        }
    }
    __syncthreads();
}

// ---------------- persistent GRU ----------------
__global__ __launch_bounds__(192, 1) void gru_kernel(
    const float* __restrict__ gi, const float* __restrict__ whh,
    const float* __restrict__ bhh, float* __restrict__ x)
{
    __shared__ float hs[2048];
    __shared__ float sgh[48];
    __shared__ float sbh[24];
    const int tid = threadIdx.x;
    const int base = blockIdx.x * 8;
    const int r = tid >> 3, j = tid & 7;
    const int gg = r >> 3, ddim = r & 7;

    float4 wreg[32];
    const float* wrow = whh + (size_t)(gg * 1024 + base + ddim) * 1024;
#pragma unroll
    for (int i = 0; i < 32; i++)
        wreg[i] = *(const float4*)(wrow + (i * 8 + j) * 4);

    if (tid < 24) sbh[tid] = bhh[(tid >> 3) * 1024 + base + (tid & 7)];
    if (tid < 16) {
        int b = tid & 1, d0 = base + (tid >> 1);
        g_h[0][2 * d0 + b] = 0.f;
    }
    gbar(1);

    for (int s = 0; s < SS; s++) {
        const int rb = s & 1, wb = rb ^ 1;

        float ir = 0.f, iz = 0.f, inn = 0.f;
        if (tid < 16) {
            int b = tid & 1, d0 = tid >> 1;
            int dg = base + d0;
            const float* gim = gi + ((size_t)b * SS + s) * 3072;
            ir  = __ldcg(gim + dg);
            iz  = __ldcg(gim + 1024 + dg);
            inn = __ldcg(gim + 2048 + dg);
        }

        for (int idx = tid; idx < 512; idx += 192)
            ((float4*)hs)[idx] = __ldcg((const float4*)&g_h[rb][0] + idx);
        __syncthreads();

        unsigned long long acc = 0ull;
#pragma unroll
        for (int i = 0; i < 32; i++) {
            int c4 = i * 8 + j;
            float4 hA = ((const float4*)hs)[c4 * 2];
            float4 hB = ((const float4*)hs)[c4 * 2 + 1];
            float4 w = wreg[i];
            ffma2(acc, pk2(w.x, w.x), pk2(hA.x, hA.y));
            ffma2(acc, pk2(w.y, w.y), pk2(hA.z, hA.w));
            ffma2(acc, pk2(w.z, w.z), pk2(hB.x, hB.y));
            ffma2(acc, pk2(w.w, w.w), pk2(hB.z, hB.w));
        }
        float2 a2 = unpk(acc);
        float acc0 = a2.x, acc1 = a2.y;
#pragma unroll
        for (int o = 4; o; o >>= 1) {
            acc0 += __shfl_down_sync(0xffffffffu, acc0, o);
            acc1 += __shfl_down_sync(0xffffffffu, acc1, o);
        }
        if (j == 0) { sgh[r * 2] = acc0 + sbh[r]; sgh[r * 2 + 1] = acc1 + sbh[r]; }
        __syncthreads();

        if (tid < 16) {
            int b = tid & 1, d0 = tid >> 1;
            int dg = base + d0;
            float hr = sgh[d0 * 2 + b], hz = sgh[(8 + d0) * 2 + b], hn = sgh[(16 + d0) * 2 + b];
            float rg = 1.f / (1.f + expf(-(ir + hr)));
            float zg = 1.f / (1.f + expf(-(iz + hz)));
            float ng = tanhf(inn + rg * hn);
            float hp = hs[2 * dg + b];
            float hv = (1.f - zg) * ng + zg * hp;
            __stcg(&g_h[wb][2 * dg + b], hv);
            x[((size_t)b * SS + s) * 1024 + dg] = hv;
        }
        gbar(2 + s);
    }

    if (tid == 0) {
        __threadfence();
        atomicAdd(&g_ack, 1u);
        if (blockIdx.x == 0) {
            while (*((volatile unsigned*)&g_ack) < GRU_CTAS) { }
            g_ack = 0;
            g_bar_phase = 0;
            __threadfence();
        }
    }
}

// ---------------- launch ----------------
extern "C" void kernel_launch(void* const* d_in, const int* in_sizes, int n_in,
                              void* d_out, int out_size) {
    const int*   ids     = (const int*)  d_in[0];
    const float* emb     = (const float*)d_in[1];
    const float* pos     = (const float*)d_in[2];
    const float* gru_wih = (const float*)d_in[3];
    const float* gru_whh = (const float*)d_in[4];
    const float* gru_bih = (const float*)d_in[5];
    const float* gru_bhh = (const float*)d_in[6];
    const float* syn_w   = (const float*)d_in[7];
    const float* syn_b   = (const float*)d_in[8];
    const float* out_w   = (const float*)d_in[9];
    const float* out_b   = (const float*)d_in[10];
    const float* ln_g    = (const float*)d_in[11];
    const float* ln_b    = (const float*)d_in[12];
    const float* on_g    = (const float*)d_in[13];
    const float* on_b    = (const float*)d_in[14];
    const float* head_w  = (const float*)d_in[15];
    const float* head_b  = (const float*)d_in[16];
    float* logits = (float*)d_out;

    float *xg, *yg, *gig, *psg, *hidg, *rsx, *rsh, *rsy;
    __nv_bfloat16 *wihhi, *wihlo, *xhi, *xlo;
    char4 *w8syn, *w8out, *w8head, *xa8, *xb8, *ha8, *hb8, *ya8, *yb8;
    cudaGetSymbolAddress((void**)&xg,   g_x);
    cudaGetSymbolAddress((void**)&yg,   g_y);
    cudaGetSymbolAddress((void**)&gig,  g_gi);
    cudaGetSymbolAddress((void**)&psg,  g_psum);
    cudaGetSymbolAddress((void**)&hidg, g_hid);
    cudaGetSymbolAddress((void**)&wihhi, g_wihhi);
    cudaGetSymbolAddress((void**)&wihlo, g_wihlo);
    cudaGetSymbolAddress((void**)&xhi, g_xhi);
    cudaGetSymbolAddress((void**)&xlo, g_xlo);
    cudaGetSymbolAddress((void**)&w8syn,  g_w8syn);
    cudaGetSymbolAddress((void**)&w8out,  g_w8out);
    cudaGetSymbolAddress((void**)&w8head, g_w8head);
    cudaGetSymbolAddress((void**)&xa8, g_xa8);
    cudaGetSymbolAddress((void**)&xb8, g_xb8);
    cudaGetSymbolAddress((void**)&ha8, g_ha8);
    cudaGetSymbolAddress((void**)&hb8, g_hb8);
    cudaGetSymbolAddress((void**)&ya8, g_ya8);
    cudaGetSymbolAddress((void**)&yb8, g_yb8);
    cudaGetSymbolAddress((void**)&rsx, g_rsx);
    cudaGetSymbolAddress((void**)&rsh, g_rsh);
    cudaGetSymbolAddress((void**)&rsy, g_rsy);

    static cudaStream_t s1, s2;
    static cudaEvent_t evRoot, ev1, ev2;
    static bool init_done = false;
    if (!init_done) {
        cudaFuncSetAttribute(bgemm_hl, cudaFuncAttributeMaxDynamicSharedMemorySize, 81920);
        cudaFuncSetAttribute(igemm<true >, cudaFuncAttributeMaxDynamicSharedMemorySize, IG_SMEM);
        cudaFuncSetAttribute(igemm<false>, cudaFuncAttributeMaxDynamicSharedMemorySize, IG_SMEM);
        cudaStreamCreateWithFlags(&s1, cudaStreamNonBlocking);
        cudaStreamCreateWithFlags(&s2, cudaStreamNonBlocking);
        cudaEventCreateWithFlags(&evRoot, cudaEventDisableTiming);
        cudaEventCreateWithFlags(&ev1, cudaEventDisableTiming);
        cudaEventCreateWithFlags(&ev2, cudaEventDisableTiming);
        init_done = true;
    }

    long nVD4 = (long)VV * DD / 4, nND4 = (long)NNH * DD / 4;
    int n4wih = 3 * DD * DD / 4;

    cudaEventRecord(evRoot, 0);
    cudaStreamWaitEvent(s1, evRoot, 0);
    cudaStreamWaitEvent(s2, evRoot, 0);

    // main stream first (launch #6 = gru_kernel for ncu -s 5 -c 1)
    hilo_quant<<<n4wih / 256, 256>>>((const float4*)gru_wih, (ushort4*)wihhi, (ushort4*)wihlo, n4wih);
    absmean_part<<<512, 256>>>((const float4*)emb, nVD4, 0);
    absmean_final<<<1, 256>>>(0);
    embed_kernel<<<4096, 256>>>(ids, emb, pos, xg, xhi, xlo);
    bgemm_hl<<<dim3(3072 / 128, MROWS / 128, 1), 256, 81920>>>(
        xhi, xlo, wihhi, wihlo, gig, gru_bih, MROWS, 3072, DD, DD);
    gru_kernel<<<GRU_CTAS, 192>>>(gig, gru_whh, gru_bhh, xg);
    x_quant8<<<MROWS, 256>>>((const float4*)xg, xa8, xb8, rsx);

    // side stream 1: layer weight scales + int8 quantization
    for (int l = 0; l < 4; l++) {
        absmean_part<<<512, 256, 0, s1>>>((const float4*)(syn_w + (size_t)l * NNH * DD), nND4, 2 + l);
        absmean_part<<<512, 256, 0, s1>>>((const float4*)(out_w + (size_t)l * DD * NNH), nND4, 6 + l);
    }
    absmean_final<<<8, 256, 0, s1>>>(2);
    for (int l = 0; l < 4; l++) {
        tern_quant8<<<(int)(nND4 / 256), 256, 0, s1>>>((const float4*)(syn_w + (size_t)l * NNH * DD),
                                                       w8syn + (size_t)l * NNH * DD / 4, 2 + l, (int)nND4);
        tern_quant8<<<(int)(nND4 / 256), 256, 0, s1>>>((const float4*)(out_w + (size_t)l * DD * NNH),
                                                       w8out + (size_t)l * DD * NNH / 4, 6 + l, (int)nND4);
    }
    cudaEventRecord(ev1, s1);

    // side stream 2: head scale + int8 quantization
    absmean_part<<<512, 256, 0, s2>>>((const float4*)head_w, nVD4, 1);
    absmean_final<<<1, 256, 0, s2>>>(1);
    tern_quant8<<<(int)(nVD4 / 256), 256, 0, s2>>>((const float4*)head_w, w8head, 1, (int)nVD4);
    cudaEventRecord(ev2, s2);

    // join layer-weight stream, MLP (int8 IMMA)
    cudaStreamWaitEvent(0, ev1, 0);
    for (int l = 0; l < 4; l++) {
        igemm<true><<<dim3(NNH / 128, MROWS / 128, 1), 256, IG_SMEM>>>(
            (const char*)xa8, (const char*)xb8, (const char*)(w8syn + (size_t)l * NNH * DD / 4),
            rsx, hidg, syn_b + (size_t)l * NNH, MROWS, NNH, DD, DD, 2 + l);
        hid_quant8<<<MROWS, 256>>>((const float4*)hidg, ha8, hb8, rsh);
        igemm<false><<<dim3(DD / 128, MROWS / 128, 4), 256, IG_SMEM>>>(
            (const char*)ha8, (const char*)hb8, (const char*)(w8out + (size_t)l * DD * NNH / 4),
            rsh, psg, (const float*)0, MROWS, DD, NNH, NNH / 4, 6 + l);
        ln_red<<<MROWS, 256>>>(out_b + (size_t)l * DD, xg, xa8, xb8, rsx,
                               ln_g + (size_t)l * DD, ln_b + (size_t)l * DD);
    }

    // join head stream, final LN + head (int8 IMMA)
    cudaStreamWaitEvent(0, ev2, 0);
    ln_kernel<<<MROWS, 256>>>(xg, yg, ya8, yb8, rsy, on_g, on_b);
    igemm<false><<<dim3(VV / 128, MROWS / 128, 1), 256, IG_SMEM>>>(
        (const char*)ya8, (const char*)yb8, (const char*)w8head,
        rsy, logits, head_b, MROWS, VV, DD, DD, 1);
}

// round 9
// speedup vs baseline: 1.3880x; 1.3880x over previous
#include <cuda_runtime.h>
#include <cuda_bf16.h>
#include <math.h>
#include <stdint.h>
#include <stddef.h>

#define SS 512
#define DD 1024
#define NNH 4096
#define VV 32000
#define MROWS 1024
#define MMDD (MROWS * DD)
#define EPSLN 1e-5f
#define GRU_CTAS 128

// ---------------- device scratch ----------------
__device__ float  g_x[MROWS * DD];
__device__ float  g_y[MROWS * DD];
__device__ float  g_gi[MROWS * 3 * DD];
__device__ float  g_psum[4 * MROWS * DD];
__device__ float  g_h[2][2 * DD];
__device__ double g_part[10 * 512];
__device__ float  g_scale[10];
__device__ float  g_scaleinv[10];
__device__ volatile unsigned g_flags[GRU_CTAS * 32];   // one 128B line per CTA
__device__ unsigned g_ack;

// bf16 buffers
__device__ __nv_bfloat16 g_qhead[VV * DD];
__device__ __nv_bfloat16 g_qsyn[4 * NNH * DD];
__device__ __nv_bfloat16 g_qout[4 * NNH * DD];
__device__ __nv_bfloat16 g_wihhi[3 * DD * DD];
__device__ __nv_bfloat16 g_wihlo[3 * DD * DD];
__device__ __nv_bfloat16 g_xhi[MROWS * DD],  g_xlo[MROWS * DD];
__device__ __nv_bfloat16 g_yhi[MROWS * DD],  g_ylo[MROWS * DD];
__device__ __nv_bfloat16 g_hhi[MROWS * NNH], g_hlo[MROWS * NNH];

// ---------------- asm helpers ----------------
#define CP16(dst, src) asm volatile("cp.async.cg.shared.global [%0], [%1], 16;" :: "r"(dst), "l"(src))
#define CPCOMMIT() asm volatile("cp.async.commit_group;")
#define CPWAIT1()  asm volatile("cp.async.wait_group 1;")
#define LDSM4(r, addr) asm volatile( \
    "ldmatrix.sync.aligned.m8n8.x4.shared.b16 {%0,%1,%2,%3}, [%4];" \
    : "=r"((r)[0]), "=r"((r)[1]), "=r"((r)[2]), "=r"((r)[3]) : "r"(addr))
#define MMA16816(d, a, b0, b1) asm volatile( \
    "mma.sync.aligned.m16n8k16.row.col.f32.bf16.bf16.f32 " \
    "{%0,%1,%2,%3},{%4,%5,%6,%7},{%8,%9},{%0,%1,%2,%3};" \
    : "+f"((d)[0]), "+f"((d)[1]), "+f"((d)[2]), "+f"((d)[3]) \
    : "r"((a)[0]), "r"((a)[1]), "r"((a)[2]), "r"((a)[3]), "r"(b0), "r"(b1))

__device__ __forceinline__ unsigned short bf16bits(float x) {
    return __bfloat16_as_ushort(__float2bfloat16(x));
}
__device__ __forceinline__ unsigned long long pk2(float x, float y) {
    unsigned long long r;
    asm("mov.b64 %0, {%1, %2};" : "=l"(r) : "f"(x), "f"(y));
    return r;
}
__device__ __forceinline__ void ffma2(unsigned long long& d, unsigned long long a, unsigned long long b) {
    asm("fma.rn.f32x2 %0, %1, %2, %0;" : "+l"(d) : "l"(a), "l"(b));
}
__device__ __forceinline__ float2 unpk(unsigned long long v) {
    float2 f;
    asm("mov.b64 {%0, %1}, %2;" : "=f"(f.x), "=f"(f.y) : "l"(v));
    return f;
}

// ---------------- abs-mean scale ----------------
__global__ __launch_bounds__(256, 2) void absmean_part(const float4* __restrict__ src, long n4, int slot) {
    __shared__ double sred[256];
    double a[8];
#pragma unroll
    for (int c = 0; c < 8; c++) a[c] = 0.0;
    const long stride = (long)gridDim.x * 256;
    long i = (long)blockIdx.x * 256 + threadIdx.x;
    for (; i + 7 * stride < n4; i += 8 * stride) {
        float4 v[8];
#pragma unroll
        for (int c = 0; c < 8; c++) v[c] = src[i + c * stride];
#pragma unroll
        for (int c = 0; c < 8; c++)
            a[c] += (double)(fabsf(v[c].x) + fabsf(v[c].y)) + (double)(fabsf(v[c].z) + fabsf(v[c].w));
    }
    for (; i < n4; i += stride) {
        float4 v = src[i];
        a[0] += (double)(fabsf(v.x) + fabsf(v.y)) + (double)(fabsf(v.z) + fabsf(v.w));
    }
    sred[threadIdx.x] = ((a[0] + a[1]) + (a[2] + a[3])) + ((a[4] + a[5]) + (a[6] + a[7]));
    __syncthreads();
#pragma unroll
    for (int o = 128; o > 0; o >>= 1) {
        if ((int)threadIdx.x < o) sred[threadIdx.x] += sred[threadIdx.x + o];
        __syncthreads();
    }
    if (threadIdx.x == 0) g_part[slot * 512 + blockIdx.x] = sred[0];
}

__global__ void absmean_final(int base) {
    __shared__ double sred[256];
    int slot = base + blockIdx.x, t = threadIdx.x;
    sred[t] = g_part[slot * 512 + t] + g_part[slot * 512 + 256 + t];
    __syncthreads();
#pragma unroll
    for (int o = 128; o > 0; o >>= 1) {
        if (t < o) sred[t] += sred[t + o];
        __syncthreads();
    }
    if (t == 0) {
        double cnt = (slot < 2) ? (double)VV * DD : (double)NNH * DD;
        double s = sred[0] / cnt + 1e-8;
        g_scale[slot]    = (float)s;
        g_scaleinv[slot] = (float)(1.0 / s);
    }
}

// ---------------- weight quantization ----------------
__global__ void tern_quant(const float4* __restrict__ w, ushort4* __restrict__ q,
                           int slot, int n4) {
    int i = blockIdx.x * 256 + threadIdx.x;
    if (i >= n4) return;
    float inv = g_scaleinv[slot];
    float4 v = w[i];
    ushort4 o;
    o.x = bf16bits(rintf(fminf(fmaxf(v.x * inv, -1.f), 1.f)));
    o.y = bf16bits(rintf(fminf(fmaxf(v.y * inv, -1.f), 1.f)));
    o.z = bf16bits(rintf(fminf(fmaxf(v.z * inv, -1.f), 1.f)));
    o.w = bf16bits(rintf(fminf(fmaxf(v.w * inv, -1.f), 1.f)));
    q[i] = o;
}

__global__ void hilo_quant(const float4* __restrict__ w, ushort4* __restrict__ hi,
                           ushort4* __restrict__ lo, int n4) {
    int i = blockIdx.x * 256 + threadIdx.x;
    if (i >= n4) return;
    float4 v = w[i];
    ushort4 h, l;
    __nv_bfloat16 hb;
    hb = __float2bfloat16(v.x); h.x = __bfloat16_as_ushort(hb); l.x = bf16bits(v.x - __bfloat162float(hb));
    hb = __float2bfloat16(v.y); h.y = __bfloat16_as_ushort(hb); l.y = bf16bits(v.y - __bfloat162float(hb));
    hb = __float2bfloat16(v.z); h.z = __bfloat16_as_ushort(hb); l.z = bf16bits(v.z - __bfloat162float(hb));
    hb = __float2bfloat16(v.w); h.w = __bfloat16_as_ushort(hb); l.w = bf16bits(v.w - __bfloat162float(hb));
    hi[i] = h; lo[i] = l;
}

// ---------------- embedding ----------------
__global__ void embed_kernel(const int* __restrict__ ids, const float* __restrict__ emb,
                             const float* __restrict__ pos, float* __restrict__ x,
                             __nv_bfloat16* __restrict__ xhi, __nv_bfloat16* __restrict__ xlo) {
    int i = blockIdx.x * 256 + threadIdx.x;
    int d = i & (DD - 1);
    int s = (i >> 10) & (SS - 1);
    int b = i >> 19;
    int tok = ids[b * SS + s];
    float w = emb[(size_t)tok * DD + d];
    float tn = g_scale[0] * rintf(fminf(fmaxf(w * g_scaleinv[0], -1.f), 1.f));
    float v = tn + pos[s * DD + d];
    x[i] = v;
    __nv_bfloat16 h = __float2bfloat16(v);
    xhi[i] = h;
    xlo[i] = __float2bfloat16(v - __bfloat162float(h));
}

// ---------------- bf16 tensor-core GEMM NT ----------------
template<int MODE, bool TERN, bool RELU, bool OUT_HILO>
__global__ __launch_bounds__(256) void bgemm(
    const __nv_bfloat16* __restrict__ Ahi, const __nv_bfloat16* __restrict__ Alo,
    const __nv_bfloat16* __restrict__ Bhi, const __nv_bfloat16* __restrict__ Blo,
    float* __restrict__ C, __nv_bfloat16* __restrict__ Chi, __nv_bfloat16* __restrict__ Clo,
    const float* __restrict__ bias, const float* __restrict__ res,
    int M, int N, int Kld, int kLen, int scaleIdx)
{
    constexpr int SZ = 128 * 40;
    extern __shared__ __align__(16) __nv_bfloat16 smb[];
    __nv_bfloat16* sAhi = smb;
    __nv_bfloat16* sAlo = smb + 2 * SZ;
    __nv_bfloat16* sBhi = smb + 4 * SZ;
    __nv_bfloat16* sBlo = smb + 6 * SZ;

    const int t = threadIdx.x;
    const int lane = t & 31;
    const int w = t >> 5;
    const int warpM = (w >> 1) << 5;
    const int warpN = (w & 1) << 6;
    const int bm = blockIdx.y << 7, bn = blockIdx.x << 7;
    const int kOff = blockIdx.z * kLen;
    if (gridDim.z > 1) C += (size_t)blockIdx.z * ((size_t)M * N);

    const __nv_bfloat16* gAhi = Ahi + (size_t)bm * Kld + kOff;
    const __nv_bfloat16* gAlo = Alo + (size_t)bm * Kld + kOff;
    const __nv_bfloat16* gBhi = Bhi + (size_t)bn * Kld + kOff;
    const __nv_bfloat16* gBlo = (MODE == 1) ? (Blo + (size_t)bn * Kld + kOff) : (const __nv_bfloat16*)0;

    const unsigned uAhi = (unsigned)__cvta_generic_to_shared(sAhi);
    const unsigned uAlo = (unsigned)__cvta_generic_to_shared(sAlo);
    const unsigned uBhi = (unsigned)__cvta_generic_to_shared(sBhi);
    const unsigned uBlo = (MODE == 1) ? (unsigned)__cvta_generic_to_shared(sBlo) : 0u;

    const int lrow = t >> 2;
    const int lcol = (t & 3) << 3;

    float acc[2][8][4];
#pragma unroll
    for (int i = 0; i < 2; i++)
#pragma unroll
        for (int j = 0; j < 8; j++)
#pragma unroll
            for (int p = 0; p < 4; p++) acc[i][j][p] = 0.f;

    const int NS = kLen >> 5;

    {
#pragma unroll
        for (int h = 0; h < 2; h++) {
            int row = lrow + (h << 6);
            size_t go = (size_t)row * Kld + lcol;
            unsigned so = ((unsigned)(row * 40 + lcol) << 1);
            CP16(uAhi + so, gAhi + go);
            CP16(uAlo + so, gAlo + go);
            CP16(uBhi + so, gBhi + go);
            if (MODE == 1) CP16(uBlo + so, gBlo + go);
        }
        CPCOMMIT();
    }

    for (int s = 0; s < NS; s++) {
        if (s + 1 < NS) {
            int k0 = (s + 1) << 5, buf = (s + 1) & 1;
#pragma unroll
            for (int h = 0; h < 2; h++) {
                int row = lrow + (h << 6);
                size_t go = (size_t)row * Kld + k0 + lcol;
                unsigned so = ((unsigned)(row * 40 + lcol) << 1) + (unsigned)buf * (SZ << 1);
                CP16(uAhi + so, gAhi + go);
                CP16(uAlo + so, gAlo + go);
                CP16(uBhi + so, gBhi + go);
                if (MODE == 1) CP16(uBlo + so, gBlo + go);
            }
        }
        CPCOMMIT();
        CPWAIT1();
        __syncthreads();

        unsigned bufOff = (unsigned)(s & 1) * (SZ << 1);
#pragma unroll
        for (int kk = 0; kk < 32; kk += 16) {
            uint32_t ah[2][4], al[2][4], bh[4][4], bl[4][4];
#pragma unroll
            for (int mt = 0; mt < 2; mt++) {
                unsigned ra = ((unsigned)((warpM + (mt << 4) + (lane & 15)) * 40 + kk + ((lane >> 4) << 3)) << 1) + bufOff;
                LDSM4(ah[mt], uAhi + ra);
                LDSM4(al[mt], uAlo + ra);
            }
#pragma unroll
            for (int bj = 0; bj < 4; bj++) {
                unsigned rb = ((unsigned)((warpN + (bj << 4) + ((lane >> 4) << 3) + (lane & 7)) * 40 + kk + (((lane >> 3) & 1) << 3)) << 1) + bufOff;
                LDSM4(bh[bj], uBhi + rb);
                if (MODE == 1) LDSM4(bl[bj], uBlo + rb);
            }
#pragma unroll
            for (int mt = 0; mt < 2; mt++)
#pragma unroll
                for (int nt = 0; nt < 8; nt++) {
                    uint32_t b0 = bh[nt >> 1][(nt & 1) << 1];
                    uint32_t b1 = bh[nt >> 1][((nt & 1) << 1) + 1];
                    MMA16816(acc[mt][nt], ah[mt], b0, b1);
                    MMA16816(acc[mt][nt], al[mt], b0, b1);
                    if (MODE == 1) {
                        uint32_t c0 = bl[nt >> 1][(nt & 1) << 1];
                        uint32_t c1 = bl[nt >> 1][((nt & 1) << 1) + 1];
                        MMA16816(acc[mt][nt], ah[mt], c0, c1);
                    }
                }
        }
        __syncthreads();
    }

    float sc = TERN ? g_scale[scaleIdx] : 1.f;
#pragma unroll
    for (int mt = 0; mt < 2; mt++)
#pragma unroll
        for (int nt = 0; nt < 8; nt++) {
            int row = bm + warpM + (mt << 4) + (lane >> 2);
            int col = bn + warpN + (nt << 3) + ((lane & 3) << 1);
#pragma unroll
            for (int half = 0; half < 2; half++) {
                int r = row + half * 8;
                float v0 = acc[mt][nt][half * 2 + 0];
                float v1 = acc[mt][nt][half * 2 + 1];
                if (TERN) { v0 *= sc; v1 *= sc; }
                if (bias) { v0 += bias[col]; v1 += bias[col + 1]; }
                if (res)  { v0 += res[(size_t)r * N + col]; v1 += res[(size_t)r * N + col + 1]; }
                if (RELU) { v0 = fmaxf(v0, 0.f); v1 = fmaxf(v1, 0.f); }
                if (OUT_HILO) {
                    __nv_bfloat16 h0 = __float2bfloat16(v0);
                    __nv_bfloat16 h1 = __float2bfloat16(v1);
                    Chi[(size_t)r * N + col]     = h0;
                    Chi[(size_t)r * N + col + 1] = h1;
                    Clo[(size_t)r * N + col]     = __float2bfloat16(v0 - __bfloat162float(h0));
                    Clo[(size_t)r * N + col + 1] = __float2bfloat16(v1 - __bfloat162float(h1));
                } else {
                    C[(size_t)r * N + col]     = v0;
                    C[(size_t)r * N + col + 1] = v1;
                }
            }
        }
}

// ---------------- fused split-K reduce + residual + LayerNorm ----------------
__global__ void ln_red(const float* __restrict__ bias, float* __restrict__ x,
                       __nv_bfloat16* __restrict__ ohi, __nv_bfloat16* __restrict__ olo,
                       const float* __restrict__ gamma, const float* __restrict__ beta)
{
    __shared__ float sred[256];
    const int row = blockIdx.x, t = threadIdx.x;
    const size_t off = (size_t)row * DD;
    float4 p0 = ((const float4*)(g_psum + off))[t];
    float4 p1 = ((const float4*)(g_psum + MMDD + off))[t];
    float4 p2 = ((const float4*)(g_psum + 2 * MMDD + off))[t];
    float4 p3 = ((const float4*)(g_psum + 3 * MMDD + off))[t];
    float4 bb = ((const float4*)bias)[t];
    float4 rr = ((const float4*)(x + off))[t];
    float4 v;
    v.x = ((p0.x + p1.x) + (p2.x + p3.x)) + bb.x + rr.x;
    v.y = ((p0.y + p1.y) + (p2.y + p3.y)) + bb.y + rr.y;
    v.z = ((p0.z + p1.z) + (p2.z + p3.z)) + bb.z + rr.z;
    v.w = ((p0.w + p1.w) + (p2.w + p3.w)) + bb.w + rr.w;

    sred[t] = v.x + v.y + v.z + v.w;
    __syncthreads();
#pragma unroll
    for (int o = 128; o > 0; o >>= 1) { if (t < o) sred[t] += sred[t + o]; __syncthreads(); }
    float mean = sred[0] * (1.f / 1024.f);
    __syncthreads();
    float dx = v.x - mean, dy = v.y - mean, dz = v.z - mean, dw = v.w - mean;
    sred[t] = dx * dx + dy * dy + dz * dz + dw * dw;
    __syncthreads();
#pragma unroll
    for (int o = 128; o > 0; o >>= 1) { if (t < o) sred[t] += sred[t + o]; __syncthreads(); }
    float rstd = rsqrtf(sred[0] * (1.f / 1024.f) + EPSLN);
    float4 g = ((const float4*)gamma)[t];
    float4 b = ((const float4*)beta)[t];
    float4 o4;
    o4.x = dx * rstd * g.x + b.x;
    o4.y = dy * rstd * g.y + b.y;
    o4.z = dz * rstd * g.z + b.z;
    o4.w = dw * rstd * g.w + b.w;
    ((float4*)(x + off))[t] = o4;
    ushort4 h, l;
    __nv_bfloat16 hb;
    hb = __float2bfloat16(o4.x); h.x = __bfloat16_as_ushort(hb); l.x = bf16bits(o4.x - __bfloat162float(hb));
    hb = __float2bfloat16(o4.y); h.y = __bfloat16_as_ushort(hb); l.y = bf16bits(o4.y - __bfloat162float(hb));
    hb = __float2bfloat16(o4.z); h.z = __bfloat16_as_ushort(hb); l.z = bf16bits(o4.z - __bfloat162float(hb));
    hb = __float2bfloat16(o4.w); h.w = __bfloat16_as_ushort(hb); l.w = bf16bits(o4.w - __bfloat162float(hb));
    ((ushort4*)(ohi + off))[t] = h;
    ((ushort4*)(olo + off))[t] = l;
}

// ---------------- plain LayerNorm ----------------
__global__ void ln_kernel(const float* __restrict__ in, float* __restrict__ out,
                          __nv_bfloat16* __restrict__ ohi, __nv_bfloat16* __restrict__ olo,
                          const float* __restrict__ gamma, const float* __restrict__ beta)
{
    __shared__ float sred[256];
    const int row = blockIdx.x, t = threadIdx.x;
    const float4 v = ((const float4*)(in + (size_t)row * DD))[t];
    sred[t] = v.x + v.y + v.z + v.w;
    __syncthreads();
#pragma unroll
    for (int o = 128; o > 0; o >>= 1) { if (t < o) sred[t] += sred[t + o]; __syncthreads(); }
    float mean = sred[0] * (1.f / 1024.f);
    __syncthreads();
    float dx = v.x - mean, dy = v.y - mean, dz = v.z - mean, dw = v.w - mean;
    sred[t] = dx * dx + dy * dy + dz * dz + dw * dw;
    __syncthreads();
#pragma unroll
    for (int o = 128; o > 0; o >>= 1) { if (t < o) sred[t] += sred[t + o]; __syncthreads(); }
    float rstd = rsqrtf(sred[0] * (1.f / 1024.f) + EPSLN);
    float4 g = ((const float4*)gamma)[t];
    float4 b = ((const float4*)beta)[t];
    float4 o4;
    o4.x = dx * rstd * g.x + b.x;
    o4.y = dy * rstd * g.y + b.y;
    o4.z = dz * rstd * g.z + b.z;
    o4.w = dw * rstd * g.w + b.w;
    ((float4*)(out + (size_t)row * DD))[t] = o4;
    ushort4 h, l;
    __nv_bfloat16 hb;
    hb = __float2bfloat16(o4.x); h.x = __bfloat16_as_ushort(hb); l.x = bf16bits(o4.x - __bfloat162float(hb));
    hb = __float2bfloat16(o4.y); h.y = __bfloat16_as_ushort(hb); l.y = bf16bits(o4.y - __bfloat162float(hb));
    hb = __float2bfloat16(o4.z); h.z = __bfloat16_as_ushort(hb); l.z = bf16bits(o4.z - __bfloat162float(hb));
    hb = __float2bfloat16(o4.w); h.w = __bfloat16_as_ushort(hb); l.w = bf16bits(o4.w - __bfloat162float(hb));
    ((ushort4*)(ohi + (size_t)row * DD))[t] = h;
    ((ushort4*)(olo + (size_t)row * DD))[t] = l;
}

// ---------------- flag-array grid barrier (no contended atomics) ----------------
__device__ __forceinline__ void gbarf(unsigned k) {
    __syncthreads();
    if (threadIdx.x == 0) {
        __threadfence();
        g_flags[(unsigned)blockIdx.x * 32] = k;
    }
    if (threadIdx.x < GRU_CTAS) {
        while (g_flags[(unsigned)threadIdx.x * 32] < k) { }
    }
    __syncthreads();
}

// ---------------- persistent GRU ----------------
__global__ __launch_bounds__(192, 1) void gru_kernel(
    const float* __restrict__ gi, const float* __restrict__ whh,
    const float* __restrict__ bhh, float* __restrict__ x,
    __nv_bfloat16* __restrict__ xhi, __nv_bfloat16* __restrict__ xlo)
{
    __shared__ float hs[2048];
    __shared__ float sgh[48];
    __shared__ float sbh[24];
    const int tid = threadIdx.x;
    const int base = blockIdx.x * 8;
    const int r = tid >> 3, j = tid & 7;
    const int gg = r >> 3, ddim = r & 7;

    float4 wreg[32];
    const float* wrow = whh + (size_t)(gg * 1024 + base + ddim) * 1024;
#pragma unroll
    for (int i = 0; i < 32; i++)
        wreg[i] = *(const float4*)(wrow + (i * 8 + j) * 4);

    if (tid < 24) sbh[tid] = bhh[(tid >> 3) * 1024 + base + (tid & 7)];
    if (tid < 16) {
        int b = tid & 1, d0 = base + (tid >> 1);
        g_h[0][2 * d0 + b] = 0.f;
    }
    gbarf(1);

    for (int s = 0; s < SS; s++) {
        const int rb = s & 1, wb = rb ^ 1;

        float ir = 0.f, iz = 0.f, inn = 0.f;
        if (tid < 16) {
            int b = tid & 1, d0 = tid >> 1;
            int dg = base + d0;
            const float* gim = gi + ((size_t)b * SS + s) * 3072;
            ir  = __ldcg(gim + dg);
            iz  = __ldcg(gim + 1024 + dg);
            inn = __ldcg(gim + 2048 + dg);
        }

        for (int idx = tid; idx < 512; idx += 192)
            ((float4*)hs)[idx] = __ldcg((const float4*)&g_h[rb][0] + idx);
        __syncthreads();

        unsigned long long ac0 = 0ull, ac1 = 0ull, ac2 = 0ull, ac3 = 0ull;
#pragma unroll
        for (int i = 0; i < 32; i++) {
            int c4 = i * 8 + j;
            float4 hA = ((const float4*)hs)[c4 * 2];
            float4 hB = ((const float4*)hs)[c4 * 2 + 1];
            float4 w = wreg[i];
            ffma2(ac0, pk2(w.x, w.x), pk2(hA.x, hA.y));
            ffma2(ac1, pk2(w.y, w.y), pk2(hA.z, hA.w));
            ffma2(ac2, pk2(w.z, w.z), pk2(hB.x, hB.y));
            ffma2(ac3, pk2(w.w, w.w), pk2(hB.z, hB.w));
        }
        float2 s0 = unpk(ac0), s1 = unpk(ac1), s2 = unpk(ac2), s3 = unpk(ac3);
        float acc0 = (s0.x + s1.x) + (s2.x + s3.x);
        float acc1 = (s0.y + s1.y) + (s2.y + s3.y);
#pragma unroll
        for (int o = 4; o; o >>= 1) {
            acc0 += __shfl_down_sync(0xffffffffu, acc0, o);
            acc1 += __shfl_down_sync(0xffffffffu, acc1, o);
        }
        if (j == 0) { sgh[r * 2] = acc0 + sbh[r]; sgh[r * 2 + 1] = acc1 + sbh[r]; }
        __syncthreads();

        if (tid < 16) {
            int b = tid & 1, d0 = tid >> 1;
            int dg = base + d0;
            float hr = sgh[d0 * 2 + b], hz = sgh[(8 + d0) * 2 + b], hn = sgh[(16 + d0) * 2 + b];
            float rg = 1.f / (1.f + expf(-(ir + hr)));
            float zg = 1.f / (1.f + expf(-(iz + hz)));
            float ng = tanhf(inn + rg * hn);
            float hp = hs[2 * dg + b];
            float hv = (1.f - zg) * ng + zg * hp;
            __stcg(&g_h[wb][2 * dg + b], hv);
            size_t m = (size_t)b * SS + s;
            x[m * 1024 + dg] = hv;
            __nv_bfloat16 hb16 = __float2bfloat16(hv);
            xhi[m * 1024 + dg] = hb16;
            xlo[m * 1024 + dg] = __float2bfloat16(hv - __bfloat162float(hb16));
        }
        if (s + 1 < SS) gbarf(2 + s);
    }

    // replay-safe reset: last acker clears flags (all CTAs have passed all polls by then)
    if (tid == 0) {
        __threadfence();
        unsigned a = atomicAdd(&g_ack, 1u);
        if (a == GRU_CTAS - 1) {
            for (int i = 0; i < GRU_CTAS; i++) g_flags[i * 32] = 0;
            __threadfence();
            g_ack = 0;
            __threadfence();
        }
    }
}

// ---------------- launch ----------------
extern "C" void kernel_launch(void* const* d_in, const int* in_sizes, int n_in,
                              void* d_out, int out_size) {
    const int*   ids     = (const int*)  d_in[0];
    const float* emb     = (const float*)d_in[1];
    const float* pos     = (const float*)d_in[2];
    const float* gru_wih = (const float*)d_in[3];
    const float* gru_whh = (const float*)d_in[4];
    const float* gru_bih = (const float*)d_in[5];
    const float* gru_bhh = (const float*)d_in[6];
    const float* syn_w   = (const float*)d_in[7];
    const float* syn_b   = (const float*)d_in[8];
    const float* out_w   = (const float*)d_in[9];
    const float* out_b   = (const float*)d_in[10];
    const float* ln_g    = (const float*)d_in[11];
    const float* ln_b    = (const float*)d_in[12];
    const float* on_g    = (const float*)d_in[13];
    const float* on_b    = (const float*)d_in[14];
    const float* head_w  = (const float*)d_in[15];
    const float* head_b  = (const float*)d_in[16];
    float* logits = (float*)d_out;

    float *xg, *yg, *gig, *psg;
    __nv_bfloat16 *qhead, *qsyn, *qout, *wihhi, *wihlo, *xhi, *xlo, *yhi, *ylo, *hhi, *hlo;
    cudaGetSymbolAddress((void**)&xg,   g_x);
    cudaGetSymbolAddress((void**)&yg,   g_y);
    cudaGetSymbolAddress((void**)&gig,  g_gi);
    cudaGetSymbolAddress((void**)&psg,  g_psum);
    cudaGetSymbolAddress((void**)&qhead, g_qhead);
    cudaGetSymbolAddress((void**)&qsyn,  g_qsyn);
    cudaGetSymbolAddress((void**)&qout,  g_qout);
    cudaGetSymbolAddress((void**)&wihhi, g_wihhi);
    cudaGetSymbolAddress((void**)&wihlo, g_wihlo);
    cudaGetSymbolAddress((void**)&xhi, g_xhi);
    cudaGetSymbolAddress((void**)&xlo, g_xlo);
    cudaGetSymbolAddress((void**)&yhi, g_yhi);
    cudaGetSymbolAddress((void**)&ylo, g_ylo);
    cudaGetSymbolAddress((void**)&hhi, g_hhi);
    cudaGetSymbolAddress((void**)&hlo, g_hlo);

    static cudaStream_t s1, s2;
    static cudaEvent_t evRoot, ev1, ev2;
    static bool init_done = false;
    if (!init_done) {
        cudaFuncSetAttribute(bgemm<1, false, false, false>, cudaFuncAttributeMaxDynamicSharedMemorySize, 81920);
        cudaFuncSetAttribute(bgemm<0, true, true,  true >, cudaFuncAttributeMaxDynamicSharedMemorySize, 61440);
        cudaFuncSetAttribute(bgemm<0, true, false, false>, cudaFuncAttributeMaxDynamicSharedMemorySize, 61440);
        cudaStreamCreateWithFlags(&s1, cudaStreamNonBlocking);
        cudaStreamCreateWithFlags(&s2, cudaStreamNonBlocking);
        cudaEventCreateWithFlags(&evRoot, cudaEventDisableTiming);
        cudaEventCreateWithFlags(&ev1, cudaEventDisableTiming);
        cudaEventCreateWithFlags(&ev2, cudaEventDisableTiming);
        init_done = true;
    }

    long nVD4 = (long)VV * DD / 4, nND4 = (long)NNH * DD / 4;
    int n4wih = 3 * DD * DD / 4;

    cudaEventRecord(evRoot, 0);
    cudaStreamWaitEvent(s1, evRoot, 0);
    cudaStreamWaitEvent(s2, evRoot, 0);

    // main stream
    hilo_quant<<<n4wih / 256, 256>>>((const float4*)gru_wih, (ushort4*)wihhi, (ushort4*)wihlo, n4wih);
    absmean_part<<<512, 256>>>((const float4*)emb, nVD4, 0);
    absmean_final<<<1, 256>>>(0);
    embed_kernel<<<4096, 256>>>(ids, emb, pos, xg, xhi, xlo);
    bgemm<1, false, false, false><<<dim3(3072 / 128, MROWS / 128, 1), 256, 81920>>>(
        xhi, xlo, wihhi, wihlo, gig, (__nv_bfloat16*)0, (__nv_bfloat16*)0,
        gru_bih, (const float*)0, MROWS, 3072, DD, DD, 0);
    gru_kernel<<<GRU_CTAS, 192>>>(gig, gru_whh, gru_bhh, xg, xhi, xlo);

    // side stream 1: layer weight scales + quantization
    for (int l = 0; l < 4; l++) {
        absmean_part<<<512, 256, 0, s1>>>((const float4*)(syn_w + (size_t)l * NNH * DD), nND4, 2 + l);
        absmean_part<<<512, 256, 0, s1>>>((const float4*)(out_w + (size_t)l * DD * NNH), nND4, 6 + l);
    }
    absmean_final<<<8, 256, 0, s1>>>(2);
    for (int l = 0; l < 4; l++) {
        tern_quant<<<(int)(nND4 / 256), 256, 0, s1>>>((const float4*)(syn_w + (size_t)l * NNH * DD),
                                                      (ushort4*)(qsyn + (size_t)l * NNH * DD), 2 + l, (int)nND4);
        tern_quant<<<(int)(nND4 / 256), 256, 0, s1>>>((const float4*)(out_w + (size_t)l * DD * NNH),
                                                      (ushort4*)(qout + (size_t)l * DD * NNH), 6 + l, (int)nND4);
    }
    cudaEventRecord(ev1, s1);

    // side stream 2: head scale + quantization
    absmean_part<<<512, 256, 0, s2>>>((const float4*)head_w, nVD4, 1);
    absmean_final<<<1, 256, 0, s2>>>(1);
    tern_quant<<<(int)(nVD4 / 256), 256, 0, s2>>>((const float4*)head_w, (ushort4*)qhead, 1, (int)nVD4);
    cudaEventRecord(ev2, s2);

    // join layer-weight stream, MLP
    cudaStreamWaitEvent(0, ev1, 0);
    for (int l = 0; l < 4; l++) {
        bgemm<0, true, true, true><<<dim3(NNH / 128, MROWS / 128, 1), 256, 61440>>>(
            xhi, xlo, qsyn + (size_t)l * NNH * DD, (const __nv_bfloat16*)0,
            (float*)0, hhi, hlo, syn_b + (size_t)l * NNH, (const float*)0,
            MROWS, NNH, DD, DD, 2 + l);
        bgemm<0, true, false, false><<<dim3(DD / 128, MROWS / 128, 4), 256, 61440>>>(
            hhi, hlo, qout + (size_t)l * DD * NNH, (const __nv_bfloat16*)0,
            psg, (__nv_bfloat16*)0, (__nv_bfloat16*)0, (const float*)0, (const float*)0,
            MROWS, DD, NNH, NNH / 4, 6 + l);
        ln_red<<<MROWS, 256>>>(out_b + (size_t)l * DD, xg, xhi, xlo,
                               ln_g + (size_t)l * DD, ln_b + (size_t)l * DD);
    }

    // join head stream, final LN + head
    cudaStreamWaitEvent(0, ev2, 0);
    ln_kernel<<<MROWS, 256>>>(xg, yg, yhi, ylo, on_g, on_b);
    bgemm<0, true, false, false><<<dim3(VV / 128, MROWS / 128, 1), 256, 61440>>>(
        yhi, ylo, qhead, (const __nv_bfloat16*)0,
        logits, (__nv_bfloat16*)0, (__nv_bfloat16*)0, head_b, (const float*)0,
        MROWS, VV, DD, DD, 1);
}

// round 10
// speedup vs baseline: 1.5718x; 1.1325x over previous
#include <cuda_runtime.h>
#include <cuda_bf16.h>
#include <cuda_fp16.h>
#include <math.h>
#include <stdint.h>
#include <stddef.h>

#define SS 512
#define DD 1024
#define NNH 4096
#define VV 32000
#define MROWS 1024
#define MMDD (MROWS * DD)
#define EPSLN 1e-5f
#define GRU_CTAS 128

// ---------------- device scratch ----------------
__device__ float  g_x[MROWS * DD];
__device__ float  g_gi[MROWS * 3 * DD];
__device__ float  g_psum[4 * MROWS * DD];
__device__ float  g_h[2][2 * DD];
__device__ double g_part[10 * 512];
__device__ float  g_scale[10];
__device__ float  g_scaleinv[10];
__device__ volatile unsigned g_flags[GRU_CTAS * 32];
__device__ unsigned g_ack;

// bf16 (in-proj only)
__device__ __nv_bfloat16 g_wihhi[3 * DD * DD];
__device__ __nv_bfloat16 g_wihlo[3 * DD * DD];
__device__ __nv_bfloat16 g_xhi[MROWS * DD], g_xlo[MROWS * DD];

// fp16 buffers
__device__ __half g_q16syn[4 * NNH * DD];
__device__ __half g_q16out[4 * NNH * DD];
__device__ __half g_q16head[VV * DD];
__device__ __half g_x16[MROWS * DD];
__device__ __half g_h16[MROWS * NNH];
__device__ __half g_y16[MROWS * DD];

// ---------------- asm helpers ----------------
#define CP16(dst, src) asm volatile("cp.async.cg.shared.global [%0], [%1], 16;" :: "r"(dst), "l"(src))
#define CPCOMMIT() asm volatile("cp.async.commit_group;")
#define CPWAIT1()  asm volatile("cp.async.wait_group 1;")
#define LDSM4(r, addr) asm volatile( \
    "ldmatrix.sync.aligned.m8n8.x4.shared.b16 {%0,%1,%2,%3}, [%4];" \
    : "=r"((r)[0]), "=r"((r)[1]), "=r"((r)[2]), "=r"((r)[3]) : "r"(addr))
#define MMA16816(d, a, b0, b1) asm volatile( \
    "mma.sync.aligned.m16n8k16.row.col.f32.bf16.bf16.f32 " \
    "{%0,%1,%2,%3},{%4,%5,%6,%7},{%8,%9},{%0,%1,%2,%3};" \
    : "+f"((d)[0]), "+f"((d)[1]), "+f"((d)[2]), "+f"((d)[3]) \
    : "r"((a)[0]), "r"((a)[1]), "r"((a)[2]), "r"((a)[3]), "r"(b0), "r"(b1))
#define HMMA16816(d, a, b0, b1) asm volatile( \
    "mma.sync.aligned.m16n8k16.row.col.f32.f16.f16.f32 " \
    "{%0,%1,%2,%3},{%4,%5,%6,%7},{%8,%9},{%0,%1,%2,%3};" \
    : "+f"((d)[0]), "+f"((d)[1]), "+f"((d)[2]), "+f"((d)[3]) \
    : "r"((a)[0]), "r"((a)[1]), "r"((a)[2]), "r"((a)[3]), "r"(b0), "r"(b1))

__device__ __forceinline__ unsigned short bf16bits(float x) {
    return __bfloat16_as_ushort(__float2bfloat16(x));
}
__device__ __forceinline__ unsigned short f16bits(float x) {
    return __half_as_ushort(__float2half(x));
}
__device__ __forceinline__ unsigned long long pk2(float x, float y) {
    unsigned long long r;
    asm("mov.b64 %0, {%1, %2};" : "=l"(r) : "f"(x), "f"(y));
    return r;
}
__device__ __forceinline__ void ffma2(unsigned long long& d, unsigned long long a, unsigned long long b) {
    asm("fma.rn.f32x2 %0, %1, %2, %0;" : "+l"(d) : "l"(a), "l"(b));
}
__device__ __forceinline__ float2 unpk(unsigned long long v) {
    float2 f;
    asm("mov.b64 {%0, %1}, %2;" : "=f"(f.x), "=f"(f.y) : "l"(v));
    return f;
}

// ---------------- abs-mean scale ----------------
__global__ __launch_bounds__(256, 2) void absmean_part(const float4* __restrict__ src, long n4, int slot) {
    __shared__ double sred[256];
    double a[8];
#pragma unroll
    for (int c = 0; c < 8; c++) a[c] = 0.0;
    const long stride = (long)gridDim.x * 256;
    long i = (long)blockIdx.x * 256 + threadIdx.x;
    for (; i + 7 * stride < n4; i += 8 * stride) {
        float4 v[8];
#pragma unroll
        for (int c = 0; c < 8; c++) v[c] = src[i + c * stride];
#pragma unroll
        for (int c = 0; c < 8; c++)
            a[c] += (double)(fabsf(v[c].x) + fabsf(v[c].y)) + (double)(fabsf(v[c].z) + fabsf(v[c].w));
    }
    for (; i < n4; i += stride) {
        float4 v = src[i];
        a[0] += (double)(fabsf(v.x) + fabsf(v.y)) + (double)(fabsf(v.z) + fabsf(v.w));
    }
    sred[threadIdx.x] = ((a[0] + a[1]) + (a[2] + a[3])) + ((a[4] + a[5]) + (a[6] + a[7]));
    __syncthreads();
#pragma unroll
    for (int o = 128; o > 0; o >>= 1) {
        if ((int)threadIdx.x < o) sred[threadIdx.x] += sred[threadIdx.x + o];
        __syncthreads();
    }
    if (threadIdx.x == 0) g_part[slot * 512 + blockIdx.x] = sred[0];
}

__global__ void absmean_final(int base) {
    __shared__ double sred[256];
    int slot = base + blockIdx.x, t = threadIdx.x;
    sred[t] = g_part[slot * 512 + t] + g_part[slot * 512 + 256 + t];
    __syncthreads();
#pragma unroll
    for (int o = 128; o > 0; o >>= 1) {
        if (t < o) sred[t] += sred[t + o];
        __syncthreads();
    }
    if (t == 0) {
        double cnt = (slot < 2) ? (double)VV * DD : (double)NNH * DD;
        double s = sred[0] / cnt + 1e-8;
        g_scale[slot]    = (float)s;
        g_scaleinv[slot] = (float)(1.0 / s);
    }
}

// ---------------- weight quantization (ternary -> fp16 exact) ----------------
__global__ void tern_quant16(const float4* __restrict__ w, ushort4* __restrict__ q,
                             int slot, int n4) {
    int i = blockIdx.x * 256 + threadIdx.x;
    if (i >= n4) return;
    float inv = g_scaleinv[slot];
    float4 v = w[i];
    ushort4 o;
    o.x = f16bits(rintf(fminf(fmaxf(v.x * inv, -1.f), 1.f)));
    o.y = f16bits(rintf(fminf(fmaxf(v.y * inv, -1.f), 1.f)));
    o.z = f16bits(rintf(fminf(fmaxf(v.z * inv, -1.f), 1.f)));
    o.w = f16bits(rintf(fminf(fmaxf(v.w * inv, -1.f), 1.f)));
    q[i] = o;
}

__global__ void hilo_quant(const float4* __restrict__ w, ushort4* __restrict__ hi,
                           ushort4* __restrict__ lo, int n4) {
    int i = blockIdx.x * 256 + threadIdx.x;
    if (i >= n4) return;
    float4 v = w[i];
    ushort4 h, l;
    __nv_bfloat16 hb;
    hb = __float2bfloat16(v.x); h.x = __bfloat16_as_ushort(hb); l.x = bf16bits(v.x - __bfloat162float(hb));
    hb = __float2bfloat16(v.y); h.y = __bfloat16_as_ushort(hb); l.y = bf16bits(v.y - __bfloat162float(hb));
    hb = __float2bfloat16(v.z); h.z = __bfloat16_as_ushort(hb); l.z = bf16bits(v.z - __bfloat162float(hb));
    hb = __float2bfloat16(v.w); h.w = __bfloat16_as_ushort(hb); l.w = bf16bits(v.w - __bfloat162float(hb));
    hi[i] = h; lo[i] = l;
}

// ---------------- embedding (hi/lo bf16 only; fp32 x is dead) ----------------
__global__ void embed_kernel(const int* __restrict__ ids, const float* __restrict__ emb,
                             const float* __restrict__ pos,
                             __nv_bfloat16* __restrict__ xhi, __nv_bfloat16* __restrict__ xlo) {
    int i = blockIdx.x * 256 + threadIdx.x;
    int d = i & (DD - 1);
    int s = (i >> 10) & (SS - 1);
    int b = i >> 19;
    int tok = ids[b * SS + s];
    float w = emb[(size_t)tok * DD + d];
    float tn = g_scale[0] * rintf(fminf(fmaxf(w * g_scaleinv[0], -1.f), 1.f));
    float v = tn + pos[s * DD + d];
    __nv_bfloat16 h = __float2bfloat16(v);
    xhi[i] = h;
    xlo[i] = __float2bfloat16(v - __bfloat162float(h));
}

// ---------------- in-proj bf16 GEMM (hi/lo x hi/lo, 3 passes) ----------------
__global__ __launch_bounds__(256) void bgemm_hl(
    const __nv_bfloat16* __restrict__ Ahi, const __nv_bfloat16* __restrict__ Alo,
    const __nv_bfloat16* __restrict__ Bhi, const __nv_bfloat16* __restrict__ Blo,
    float* __restrict__ C, const float* __restrict__ bias,
    int M, int N, int Kld, int kLen)
{
    constexpr int SZ = 128 * 40;
    extern __shared__ __align__(16) __nv_bfloat16 smb[];
    __nv_bfloat16* sAhi = smb;
    __nv_bfloat16* sAlo = smb + 2 * SZ;
    __nv_bfloat16* sBhi = smb + 4 * SZ;
    __nv_bfloat16* sBlo = smb + 6 * SZ;

    const int t = threadIdx.x;
    const int lane = t & 31;
    const int w = t >> 5;
    const int warpM = (w >> 1) << 5;
    const int warpN = (w & 1) << 6;
    const int bm = blockIdx.y << 7, bn = blockIdx.x << 7;

    const __nv_bfloat16* gAhi = Ahi + (size_t)bm * Kld;
    const __nv_bfloat16* gAlo = Alo + (size_t)bm * Kld;
    const __nv_bfloat16* gBhi = Bhi + (size_t)bn * Kld;
    const __nv_bfloat16* gBlo = Blo + (size_t)bn * Kld;

    const unsigned uAhi = (unsigned)__cvta_generic_to_shared(sAhi);
    const unsigned uAlo = (unsigned)__cvta_generic_to_shared(sAlo);
    const unsigned uBhi = (unsigned)__cvta_generic_to_shared(sBhi);
    const unsigned uBlo = (unsigned)__cvta_generic_to_shared(sBlo);

    const int lrow = t >> 2;
    const int lcol = (t & 3) << 3;

    float acc[2][8][4];
#pragma unroll
    for (int i = 0; i < 2; i++)
#pragma unroll
        for (int j = 0; j < 8; j++)
#pragma unroll
            for (int p = 0; p < 4; p++) acc[i][j][p] = 0.f;

    const int NS = kLen >> 5;
    {
#pragma unroll
        for (int h = 0; h < 2; h++) {
            int row = lrow + (h << 6);
            size_t go = (size_t)row * Kld + lcol;
            unsigned so = ((unsigned)(row * 40 + lcol) << 1);
            CP16(uAhi + so, gAhi + go);
            CP16(uAlo + so, gAlo + go);
            CP16(uBhi + so, gBhi + go);
            CP16(uBlo + so, gBlo + go);
        }
        CPCOMMIT();
    }

    for (int s = 0; s < NS; s++) {
        if (s + 1 < NS) {
            int k0 = (s + 1) << 5, buf = (s + 1) & 1;
#pragma unroll
            for (int h = 0; h < 2; h++) {
                int row = lrow + (h << 6);
                size_t go = (size_t)row * Kld + k0 + lcol;
                unsigned so = ((unsigned)(row * 40 + lcol) << 1) + (unsigned)buf * (SZ << 1);
                CP16(uAhi + so, gAhi + go);
                CP16(uAlo + so, gAlo + go);
                CP16(uBhi + so, gBhi + go);
                CP16(uBlo + so, gBlo + go);
            }
        }
        CPCOMMIT();
        CPWAIT1();
        __syncthreads();

        unsigned bufOff = (unsigned)(s & 1) * (SZ << 1);
#pragma unroll
        for (int kk = 0; kk < 32; kk += 16) {
            uint32_t ah[2][4], al[2][4], bh[4][4], bl[4][4];
#pragma unroll
            for (int mt = 0; mt < 2; mt++) {
                unsigned ra = ((unsigned)((warpM + (mt << 4) + (lane & 15)) * 40 + kk + ((lane >> 4) << 3)) << 1) + bufOff;
                LDSM4(ah[mt], uAhi + ra);
                LDSM4(al[mt], uAlo + ra);
            }
#pragma unroll
            for (int bj = 0; bj < 4; bj++) {
                unsigned rb = ((unsigned)((warpN + (bj << 4) + ((lane >> 4) << 3) + (lane & 7)) * 40 + kk + (((lane >> 3) & 1) << 3)) << 1) + bufOff;
                LDSM4(bh[bj], uBhi + rb);
                LDSM4(bl[bj], uBlo + rb);
            }
#pragma unroll
            for (int mt = 0; mt < 2; mt++)
#pragma unroll
                for (int nt = 0; nt < 8; nt++) {
                    uint32_t b0 = bh[nt >> 1][(nt & 1) << 1];
                    uint32_t b1 = bh[nt >> 1][((nt & 1) << 1) + 1];
                    MMA16816(acc[mt][nt], ah[mt], b0, b1);
                    MMA16816(acc[mt][nt], al[mt], b0, b1);
                    uint32_t c0 = bl[nt >> 1][(nt & 1) << 1];
                    uint32_t c1 = bl[nt >> 1][((nt & 1) << 1) + 1];
                    MMA16816(acc[mt][nt], ah[mt], c0, c1);
                }
        }
        __syncthreads();
    }

#pragma unroll
    for (int mt = 0; mt < 2; mt++)
#pragma unroll
        for (int nt = 0; nt < 8; nt++) {
            int row = bm + warpM + (mt << 4) + (lane >> 2);
            int col = bn + warpN + (nt << 3) + ((lane & 3) << 1);
#pragma unroll
            for (int half = 0; half < 2; half++) {
                int r = row + half * 8;
                C[(size_t)r * N + col]     = acc[mt][nt][half * 2 + 0] + bias[col];
                C[(size_t)r * N + col + 1] = acc[mt][nt][half * 2 + 1] + bias[col + 1];
            }
        }
}

// ---------------- single-pass FP16 tensor-core GEMM NT ----------------
// C[m,n] = scale * sum_k A16[m,k]*T16[n,k]  [+bias] [relu]; out fp32 or fp16
#define HG_SMEM (4 * 128 * 40 * 2)   // 40960 B

template<bool RELU, bool OUT_F16>
__global__ __launch_bounds__(256) void hgemm(
    const __half* __restrict__ A, const __half* __restrict__ B,
    float* __restrict__ C, __half* __restrict__ C16,
    const float* __restrict__ bias,
    int M, int N, int Kld, int kLen, int slot)
{
    constexpr int SZ = 128 * 40;
    extern __shared__ __align__(16) __half smh[];
    __half* sA = smh;
    __half* sB = smh + 2 * SZ;

    const int t = threadIdx.x;
    const int lane = t & 31;
    const int w = t >> 5;
    const int warpM = (w >> 1) << 5;
    const int warpN = (w & 1) << 6;
    const int bm = blockIdx.y << 7, bn = blockIdx.x << 7;
    const int kOff = blockIdx.z * kLen;
    if (gridDim.z > 1) C += (size_t)blockIdx.z * ((size_t)M * N);

    const __half* gA = A + (size_t)bm * Kld + kOff;
    const __half* gB = B + (size_t)bn * Kld + kOff;
    const unsigned uA = (unsigned)__cvta_generic_to_shared(sA);
    const unsigned uB = (unsigned)__cvta_generic_to_shared(sB);

    const int lrow = t >> 2;
    const int lcol = (t & 3) << 3;

    float acc[2][8][4];
#pragma unroll
    for (int i = 0; i < 2; i++)
#pragma unroll
        for (int j = 0; j < 8; j++)
#pragma unroll
            for (int p = 0; p < 4; p++) acc[i][j][p] = 0.f;

    const int NS = kLen >> 5;
    {
#pragma unroll
        for (int h = 0; h < 2; h++) {
            int row = lrow + (h << 6);
            size_t go = (size_t)row * Kld + lcol;
            unsigned so = ((unsigned)(row * 40 + lcol) << 1);
            CP16(uA + so, gA + go);
            CP16(uB + so, gB + go);
        }
        CPCOMMIT();
    }

    for (int s = 0; s < NS; s++) {
        if (s + 1 < NS) {
            int k0 = (s + 1) << 5, buf = (s + 1) & 1;
#pragma unroll
            for (int h = 0; h < 2; h++) {
                int row = lrow + (h << 6);
                size_t go = (size_t)row * Kld + k0 + lcol;
                unsigned so = ((unsigned)(row * 40 + lcol) << 1) + (unsigned)buf * (SZ << 1);
                CP16(uA + so, gA + go);
                CP16(uB + so, gB + go);
            }
        }
        CPCOMMIT();
        CPWAIT1();
        __syncthreads();

        unsigned bufOff = (unsigned)(s & 1) * (SZ << 1);
#pragma unroll
        for (int kk = 0; kk < 32; kk += 16) {
            uint32_t af[2][4], bf[4][4];
#pragma unroll
            for (int mt = 0; mt < 2; mt++) {
                unsigned ra = ((unsigned)((warpM + (mt << 4) + (lane & 15)) * 40 + kk + ((lane >> 4) << 3)) << 1) + bufOff;
                LDSM4(af[mt], uA + ra);
            }
#pragma unroll
            for (int bj = 0; bj < 4; bj++) {
                unsigned rb = ((unsigned)((warpN + (bj << 4) + ((lane >> 4) << 3) + (lane & 7)) * 40 + kk + (((lane >> 3) & 1) << 3)) << 1) + bufOff;
                LDSM4(bf[bj], uB + rb);
            }
#pragma unroll
            for (int mt = 0; mt < 2; mt++)
#pragma unroll
                for (int nt = 0; nt < 8; nt++) {
                    uint32_t b0 = bf[nt >> 1][(nt & 1) << 1];
                    uint32_t b1 = bf[nt >> 1][((nt & 1) << 1) + 1];
                    HMMA16816(acc[mt][nt], af[mt], b0, b1);
                }
        }
        __syncthreads();
    }

    const float sc = g_scale[slot];
#pragma unroll
    for (int mt = 0; mt < 2; mt++)
#pragma unroll
        for (int nt = 0; nt < 8; nt++) {
            int row = bm + warpM + (mt << 4) + (lane >> 2);
            int col = bn + warpN + (nt << 3) + ((lane & 3) << 1);
#pragma unroll
            for (int half = 0; half < 2; half++) {
                int r = row + half * 8;
                float v0 = acc[mt][nt][half * 2 + 0] * sc;
                float v1 = acc[mt][nt][half * 2 + 1] * sc;
                if (bias) { v0 += bias[col]; v1 += bias[col + 1]; }
                if (RELU) { v0 = fmaxf(v0, 0.f); v1 = fmaxf(v1, 0.f); }
                if (OUT_F16) {
                    C16[(size_t)r * N + col]     = __float2half(v0);
                    C16[(size_t)r * N + col + 1] = __float2half(v1);
                } else {
                    C[(size_t)r * N + col]     = v0;
                    C[(size_t)r * N + col + 1] = v1;
                }
            }
        }
}

// ---------------- fused split-K reduce + residual + LayerNorm (+fp16 out) ----------------
__global__ void ln_red(const float* __restrict__ bias, float* __restrict__ x,
                       __half* __restrict__ o16,
                       const float* __restrict__ gamma, const float* __restrict__ beta)
{
    __shared__ float sred[256];
    const int row = blockIdx.x, t = threadIdx.x;
    const size_t off = (size_t)row * DD;
    float4 p0 = ((const float4*)(g_psum + off))[t];
    float4 p1 = ((const float4*)(g_psum + MMDD + off))[t];
    float4 p2 = ((const float4*)(g_psum + 2 * MMDD + off))[t];
    float4 p3 = ((const float4*)(g_psum + 3 * MMDD + off))[t];
    float4 bb = ((const float4*)bias)[t];
    float4 rr = ((const float4*)(x + off))[t];
    float4 v;
    v.x = ((p0.x + p1.x) + (p2.x + p3.x)) + bb.x + rr.x;
    v.y = ((p0.y + p1.y) + (p2.y + p3.y)) + bb.y + rr.y;
    v.z = ((p0.z + p1.z) + (p2.z + p3.z)) + bb.z + rr.z;
    v.w = ((p0.w + p1.w) + (p2.w + p3.w)) + bb.w + rr.w;

    sred[t] = v.x + v.y + v.z + v.w;
    __syncthreads();
#pragma unroll
    for (int o = 128; o > 0; o >>= 1) { if (t < o) sred[t] += sred[t + o]; __syncthreads(); }
    float mean = sred[0] * (1.f / 1024.f);
    __syncthreads();
    float dx = v.x - mean, dy = v.y - mean, dz = v.z - mean, dw = v.w - mean;
    sred[t] = dx * dx + dy * dy + dz * dz + dw * dw;
    __syncthreads();
#pragma unroll
    for (int o = 128; o > 0; o >>= 1) { if (t < o) sred[t] += sred[t + o]; __syncthreads(); }
    float rstd = rsqrtf(sred[0] * (1.f / 1024.f) + EPSLN);
    float4 g = ((const float4*)gamma)[t];
    float4 b = ((const float4*)beta)[t];
    float4 o4;
    o4.x = dx * rstd * g.x + b.x;
    o4.y = dy * rstd * g.y + b.y;
    o4.z = dz * rstd * g.z + b.z;
    o4.w = dw * rstd * g.w + b.w;
    ((float4*)(x + off))[t] = o4;
    ushort4 h;
    h.x = f16bits(o4.x); h.y = f16bits(o4.y); h.z = f16bits(o4.z); h.w = f16bits(o4.w);
    ((ushort4*)(o16 + off))[t] = h;
}

// ---------------- final LayerNorm (fp16 out only) ----------------
__global__ void ln_final(const float* __restrict__ in, __half* __restrict__ o16,
                         const float* __restrict__ gamma, const float* __restrict__ beta)
{
    __shared__ float sred[256];
    const int row = blockIdx.x, t = threadIdx.x;
    const float4 v = ((const float4*)(in + (size_t)row * DD))[t];
    sred[t] = v.x + v.y + v.z + v.w;
    __syncthreads();
#pragma unroll
    for (int o = 128; o > 0; o >>= 1) { if (t < o) sred[t] += sred[t + o]; __syncthreads(); }
    float mean = sred[0] * (1.f / 1024.f);
    __syncthreads();
    float dx = v.x - mean, dy = v.y - mean, dz = v.z - mean, dw = v.w - mean;
    sred[t] = dx * dx + dy * dy + dz * dz + dw * dw;
    __syncthreads();
#pragma unroll
    for (int o = 128; o > 0; o >>= 1) { if (t < o) sred[t] += sred[t + o]; __syncthreads(); }
    float rstd = rsqrtf(sred[0] * (1.f / 1024.f) + EPSLN);
    float4 g = ((const float4*)gamma)[t];
    float4 b = ((const float4*)beta)[t];
    ushort4 h;
    h.x = f16bits(dx * rstd * g.x + b.x);
    h.y = f16bits(dy * rstd * g.y + b.y);
    h.z = f16bits(dz * rstd * g.z + b.z);
    h.w = f16bits(dw * rstd * g.w + b.w);
    ((ushort4*)(o16 + (size_t)row * DD))[t] = h;
}

// ---------------- flag-array grid barrier ----------------
__device__ __forceinline__ void gbarf(unsigned k) {
    __syncthreads();
    if (threadIdx.x == 0) {
        __threadfence();
        g_flags[(unsigned)blockIdx.x * 32] = k;
    }
    if (threadIdx.x < GRU_CTAS) {
        while (g_flags[(unsigned)threadIdx.x * 32] < k) { }
    }
    __syncthreads();
}

// ---------------- persistent GRU ----------------
__global__ __launch_bounds__(192, 1) void gru_kernel(
    const float* __restrict__ gi, const float* __restrict__ whh,
    const float* __restrict__ bhh, float* __restrict__ x,
    __half* __restrict__ x16)
{
    __shared__ float hs[2048];
    __shared__ float sgh[48];
    __shared__ float sbh[24];
    const int tid = threadIdx.x;
    const int base = blockIdx.x * 8;
    const int r = tid >> 3, j = tid & 7;
    const int gg = r >> 3, ddim = r & 7;

    float4 wreg[32];
    const float* wrow = whh + (size_t)(gg * 1024 + base + ddim) * 1024;
#pragma unroll
    for (int i = 0; i < 32; i++)
        wreg[i] = *(const float4*)(wrow + (i * 8 + j) * 4);

    if (tid < 24) sbh[tid] = bhh[(tid >> 3) * 1024 + base + (tid & 7)];
    if (tid < 16) {
        int b = tid & 1, d0 = base + (tid >> 1);
        g_h[0][2 * d0 + b] = 0.f;
    }
    gbarf(1);

    for (int s = 0; s < SS; s++) {
        const int rb = s & 1, wb = rb ^ 1;

        float ir = 0.f, iz = 0.f, inn = 0.f;
        if (tid < 16) {
            int b = tid & 1, d0 = tid >> 1;
            int dg = base + d0;
            const float* gim = gi + ((size_t)b * SS + s) * 3072;
            ir  = __ldcg(gim + dg);
            iz  = __ldcg(gim + 1024 + dg);
            inn = __ldcg(gim + 2048 + dg);
        }

        for (int idx = tid; idx < 512; idx += 192)
            ((float4*)hs)[idx] = __ldcg((const float4*)&g_h[rb][0] + idx);
        __syncthreads();

        unsigned long long ac0 = 0ull, ac1 = 0ull, ac2 = 0ull, ac3 = 0ull;
#pragma unroll
        for (int i = 0; i < 32; i++) {
            int c4 = i * 8 + j;
            float4 hA = ((const float4*)hs)[c4 * 2];
            float4 hB = ((const float4*)hs)[c4 * 2 + 1];
            float4 w = wreg[i];
            ffma2(ac0, pk2(w.x, w.x), pk2(hA.x, hA.y));
            ffma2(ac1, pk2(w.y, w.y), pk2(hA.z, hA.w));
            ffma2(ac2, pk2(w.z, w.z), pk2(hB.x, hB.y));
            ffma2(ac3, pk2(w.w, w.w), pk2(hB.z, hB.w));
        }
        float2 s0 = unpk(ac0), s1 = unpk(ac1), s2 = unpk(ac2), s3 = unpk(ac3);
        float acc0 = (s0.x + s1.x) + (s2.x + s3.x);
        float acc1 = (s0.y + s1.y) + (s2.y + s3.y);
#pragma unroll
        for (int o = 4; o; o >>= 1) {
            acc0 += __shfl_down_sync(0xffffffffu, acc0, o);
            acc1 += __shfl_down_sync(0xffffffffu, acc1, o);
        }
        if (j == 0) { sgh[r * 2] = acc0 + sbh[r]; sgh[r * 2 + 1] = acc1 + sbh[r]; }
        __syncthreads();

        if (tid < 16) {
            int b = tid & 1, d0 = tid >> 1;
            int dg = base + d0;
            float hr = sgh[d0 * 2 + b], hz = sgh[(8 + d0) * 2 + b], hn = sgh[(16 + d0) * 2 + b];
            float rg = 1.f / (1.f + expf(-(ir + hr)));
            float zg = 1.f / (1.f + expf(-(iz + hz)));
            float ng = tanhf(inn + rg * hn);
            float hp = hs[2 * dg + b];
            float hv = (1.f - zg) * ng + zg * hp;
            __stcg(&g_h[wb][2 * dg + b], hv);
            size_t m = (size_t)b * SS + s;
            x[m * 1024 + dg] = hv;
            x16[m * 1024 + dg] = __float2half(hv);
        }
        if (s + 1 < SS) gbarf(2 + s);
    }

    if (tid == 0) {
        __threadfence();
        unsigned a = atomicAdd(&g_ack, 1u);
        if (a == GRU_CTAS - 1) {
            for (int i = 0; i < GRU_CTAS; i++) g_flags[i * 32] = 0;
            __threadfence();
            g_ack = 0;
            __threadfence();
        }
    }
}

// ---------------- launch ----------------
extern "C" void kernel_launch(void* const* d_in, const int* in_sizes, int n_in,
                              void* d_out, int out_size) {
    const int*   ids     = (const int*)  d_in[0];
    const float* emb     = (const float*)d_in[1];
    const float* pos     = (const float*)d_in[2];
    const float* gru_wih = (const float*)d_in[3];
    const float* gru_whh = (const float*)d_in[4];
    const float* gru_bih = (const float*)d_in[5];
    const float* gru_bhh = (const float*)d_in[6];
    const float* syn_w   = (const float*)d_in[7];
    const float* syn_b   = (const float*)d_in[8];
    const float* out_w   = (const float*)d_in[9];
    const float* out_b   = (const float*)d_in[10];
    const float* ln_g    = (const float*)d_in[11];
    const float* ln_b    = (const float*)d_in[12];
    const float* on_g    = (const float*)d_in[13];
    const float* on_b    = (const float*)d_in[14];
    const float* head_w  = (const float*)d_in[15];
    const float* head_b  = (const float*)d_in[16];
    float* logits = (float*)d_out;

    float *xg, *gig, *psg;
    __nv_bfloat16 *wihhi, *wihlo, *xhi, *xlo;
    __half *q16syn, *q16out, *q16head, *x16, *h16, *y16;
    cudaGetSymbolAddress((void**)&xg,   g_x);
    cudaGetSymbolAddress((void**)&gig,  g_gi);
    cudaGetSymbolAddress((void**)&psg,  g_psum);
    cudaGetSymbolAddress((void**)&wihhi, g_wihhi);
    cudaGetSymbolAddress((void**)&wihlo, g_wihlo);
    cudaGetSymbolAddress((void**)&xhi, g_xhi);
    cudaGetSymbolAddress((void**)&xlo, g_xlo);
    cudaGetSymbolAddress((void**)&q16syn,  g_q16syn);
    cudaGetSymbolAddress((void**)&q16out,  g_q16out);
    cudaGetSymbolAddress((void**)&q16head, g_q16head);
    cudaGetSymbolAddress((void**)&x16, g_x16);
    cudaGetSymbolAddress((void**)&h16, g_h16);
    cudaGetSymbolAddress((void**)&y16, g_y16);

    static cudaStream_t s1, s2;
    static cudaEvent_t evRoot, ev1, ev2;
    static bool init_done = false;
    if (!init_done) {
        cudaFuncSetAttribute(bgemm_hl, cudaFuncAttributeMaxDynamicSharedMemorySize, 81920);
        cudaFuncSetAttribute(hgemm<true,  true >, cudaFuncAttributeMaxDynamicSharedMemorySize, HG_SMEM);
        cudaFuncSetAttribute(hgemm<false, false>, cudaFuncAttributeMaxDynamicSharedMemorySize, HG_SMEM);
        cudaStreamCreateWithFlags(&s1, cudaStreamNonBlocking);
        cudaStreamCreateWithFlags(&s2, cudaStreamNonBlocking);
        cudaEventCreateWithFlags(&evRoot, cudaEventDisableTiming);
        cudaEventCreateWithFlags(&ev1, cudaEventDisableTiming);
        cudaEventCreateWithFlags(&ev2, cudaEventDisableTiming);
        init_done = true;
    }

    long nVD4 = (long)VV * DD / 4, nND4 = (long)NNH * DD / 4;
    int n4wih = 3 * DD * DD / 4;

    cudaEventRecord(evRoot, 0);
    cudaStreamWaitEvent(s1, evRoot, 0);
    cudaStreamWaitEvent(s2, evRoot, 0);

    // main stream
    hilo_quant<<<n4wih / 256, 256>>>((const float4*)gru_wih, (ushort4*)wihhi, (ushort4*)wihlo, n4wih);
    absmean_part<<<512, 256>>>((const float4*)emb, nVD4, 0);
    absmean_final<<<1, 256>>>(0);
    embed_kernel<<<4096, 256>>>(ids, emb, pos, xhi, xlo);
    bgemm_hl<<<dim3(3072 / 128, MROWS / 128, 1), 256, 81920>>>(
        xhi, xlo, wihhi, wihlo, gig, gru_bih, MROWS, 3072, DD, DD);
    gru_kernel<<<GRU_CTAS, 192>>>(gig, gru_whh, gru_bhh, xg, x16);

    // side stream 1: layer weight scales + fp16 quantization
    for (int l = 0; l < 4; l++) {
        absmean_part<<<512, 256, 0, s1>>>((const float4*)(syn_w + (size_t)l * NNH * DD), nND4, 2 + l);
        absmean_part<<<512, 256, 0, s1>>>((const float4*)(out_w + (size_t)l * DD * NNH), nND4, 6 + l);
    }
    absmean_final<<<8, 256, 0, s1>>>(2);
    for (int l = 0; l < 4; l++) {
        tern_quant16<<<(int)(nND4 / 256), 256, 0, s1>>>((const float4*)(syn_w + (size_t)l * NNH * DD),
                                                        (ushort4*)(q16syn + (size_t)l * NNH * DD), 2 + l, (int)nND4);
        tern_quant16<<<(int)(nND4 / 256), 256, 0, s1>>>((const float4*)(out_w + (size_t)l * DD * NNH),
                                                        (ushort4*)(q16out + (size_t)l * DD * NNH), 6 + l, (int)nND4);
    }
    cudaEventRecord(ev1, s1);

    // side stream 2: head scale + fp16 quantization
    absmean_part<<<512, 256, 0, s2>>>((const float4*)head_w, nVD4, 1);
    absmean_final<<<1, 256, 0, s2>>>(1);
    tern_quant16<<<(int)(nVD4 / 256), 256, 0, s2>>>((const float4*)head_w, (ushort4*)q16head, 1, (int)nVD4);
    cudaEventRecord(ev2, s2);

    // join layer-weight stream, MLP (single-pass fp16)
    cudaStreamWaitEvent(0, ev1, 0);
    for (int l = 0; l < 4; l++) {
        hgemm<true, true><<<dim3(NNH / 128, MROWS / 128, 1), 256, HG_SMEM>>>(
            x16, q16syn + (size_t)l * NNH * DD, (float*)0, h16,
            syn_b + (size_t)l * NNH, MROWS, NNH, DD, DD, 2 + l);
        hgemm<false, false><<<dim3(DD / 128, MROWS / 128, 4), 256, HG_SMEM>>>(
            h16, q16out + (size_t)l * DD * NNH, psg, (__half*)0,
            (const float*)0, MROWS, DD, NNH, NNH / 4, 6 + l);
        ln_red<<<MROWS, 256>>>(out_b + (size_t)l * DD, xg, x16,
                               ln_g + (size_t)l * DD, ln_b + (size_t)l * DD);
    }

    // join head stream, final LN + head (single-pass fp16)
    cudaStreamWaitEvent(0, ev2, 0);
    ln_final<<<MROWS, 256>>>(xg, y16, on_g, on_b);
    hgemm<false, false><<<dim3(VV / 128, MROWS / 128, 1), 256, HG_SMEM>>>(
        y16, q16head, logits, (__half*)0, head_b, MROWS, VV, DD, DD, 1);
}

// round 11
// speedup vs baseline: 1.6510x; 1.0504x over previous
#include <cuda_runtime.h>
#include <cuda_bf16.h>
#include <cuda_fp16.h>
#include <math.h>
#include <stdint.h>
#include <stddef.h>

#define SS 512
#define DD 1024
#define NNH 4096
#define VV 32000
#define MROWS 1024
#define MMDD (MROWS * DD)
#define EPSLN 1e-5f
#define GRU_CTAS 128

// ---------------- device scratch ----------------
__device__ float  g_x[MROWS * DD];
__device__ float  g_gi[MROWS * 3 * DD];
__device__ float  g_psum[4 * MROWS * DD];
__device__ float  g_h[2][2 * DD];
__device__ double g_part[10 * 512];
__device__ float  g_scale[10];
__device__ float  g_scaleinv[10];
__device__ volatile unsigned g_flags[GRU_CTAS * 32];
__device__ unsigned g_ack;

// fp16 buffers
__device__ __half g_w16ih[3 * DD * DD];
__device__ __half g_q16syn[4 * NNH * DD];
__device__ __half g_q16out[4 * NNH * DD];
__device__ __half g_q16head[VV * DD];
__device__ __half g_x16[MROWS * DD];
__device__ __half g_h16[MROWS * NNH];
__device__ __half g_y16[MROWS * DD];

// ---------------- asm helpers ----------------
#define CP16(dst, src) asm volatile("cp.async.cg.shared.global [%0], [%1], 16;" :: "r"(dst), "l"(src))
#define CPCOMMIT() asm volatile("cp.async.commit_group;")
#define CPWAIT_1() asm volatile("cp.async.wait_group 1;")
#define LDSM4(r, addr) asm volatile( \
    "ldmatrix.sync.aligned.m8n8.x4.shared.b16 {%0,%1,%2,%3}, [%4];" \
    : "=r"((r)[0]), "=r"((r)[1]), "=r"((r)[2]), "=r"((r)[3]) : "r"(addr))
#define HMMA16816(d, a, b0, b1) asm volatile( \
    "mma.sync.aligned.m16n8k16.row.col.f32.f16.f16.f32 " \
    "{%0,%1,%2,%3},{%4,%5,%6,%7},{%8,%9},{%0,%1,%2,%3};" \
    : "+f"((d)[0]), "+f"((d)[1]), "+f"((d)[2]), "+f"((d)[3]) \
    : "r"((a)[0]), "r"((a)[1]), "r"((a)[2]), "r"((a)[3]), "r"(b0), "r"(b1))

__device__ __forceinline__ unsigned short f16bits(float x) {
    return __half_as_ushort(__float2half(x));
}
__device__ __forceinline__ unsigned long long pk2(float x, float y) {
    unsigned long long r;
    asm("mov.b64 %0, {%1, %2};" : "=l"(r) : "f"(x), "f"(y));
    return r;
}
__device__ __forceinline__ void ffma2(unsigned long long& d, unsigned long long a, unsigned long long b) {
    asm("fma.rn.f32x2 %0, %1, %2, %0;" : "+l"(d) : "l"(a), "l"(b));
}
__device__ __forceinline__ float2 unpk(unsigned long long v) {
    float2 f;
    asm("mov.b64 {%0, %1}, %2;" : "=f"(f.x), "=f"(f.y) : "l"(v));
    return f;
}

// ---------------- abs-mean scale ----------------
__global__ __launch_bounds__(256, 2) void absmean_part(const float4* __restrict__ src, long n4, int slot) {
    __shared__ double sred[256];
    double a[8];
#pragma unroll
    for (int c = 0; c < 8; c++) a[c] = 0.0;
    const long stride = (long)gridDim.x * 256;
    long i = (long)blockIdx.x * 256 + threadIdx.x;
    for (; i + 7 * stride < n4; i += 8 * stride) {
        float4 v[8];
#pragma unroll
        for (int c = 0; c < 8; c++) v[c] = src[i + c * stride];
#pragma unroll
        for (int c = 0; c < 8; c++)
            a[c] += (double)(fabsf(v[c].x) + fabsf(v[c].y)) + (double)(fabsf(v[c].z) + fabsf(v[c].w));
    }
    for (; i < n4; i += stride) {
        float4 v = src[i];
        a[0] += (double)(fabsf(v.x) + fabsf(v.y)) + (double)(fabsf(v.z) + fabsf(v.w));
    }
    sred[threadIdx.x] = ((a[0] + a[1]) + (a[2] + a[3])) + ((a[4] + a[5]) + (a[6] + a[7]));
    __syncthreads();
#pragma unroll
    for (int o = 128; o > 0; o >>= 1) {
        if ((int)threadIdx.x < o) sred[threadIdx.x] += sred[threadIdx.x + o];
        __syncthreads();
    }
    if (threadIdx.x == 0) g_part[slot * 512 + blockIdx.x] = sred[0];
}

__global__ void absmean_final(int base) {
    __shared__ double sred[256];
    int slot = base + blockIdx.x, t = threadIdx.x;
    sred[t] = g_part[slot * 512 + t] + g_part[slot * 512 + 256 + t];
    __syncthreads();
#pragma unroll
    for (int o = 128; o > 0; o >>= 1) {
        if (t < o) sred[t] += sred[t + o];
        __syncthreads();
    }
    if (t == 0) {
        double cnt = (slot < 2) ? (double)VV * DD : (double)NNH * DD;
        double s = sred[0] / cnt + 1e-8;
        g_scale[slot]    = (float)s;
        g_scaleinv[slot] = (float)(1.0 / s);
    }
}

// ---------------- weight conversion ----------------
__global__ void tern_quant16(const float4* __restrict__ w, ushort4* __restrict__ q,
                             int slot, int n4) {
    int i = blockIdx.x * 256 + threadIdx.x;
    if (i >= n4) return;
    float inv = g_scaleinv[slot];
    float4 v = w[i];
    ushort4 o;
    o.x = f16bits(rintf(fminf(fmaxf(v.x * inv, -1.f), 1.f)));
    o.y = f16bits(rintf(fminf(fmaxf(v.y * inv, -1.f), 1.f)));
    o.z = f16bits(rintf(fminf(fmaxf(v.z * inv, -1.f), 1.f)));
    o.w = f16bits(rintf(fminf(fmaxf(v.w * inv, -1.f), 1.f)));
    q[i] = o;
}

__global__ void f16cvt(const float4* __restrict__ w, ushort4* __restrict__ q, int n4) {
    int i = blockIdx.x * 256 + threadIdx.x;
    if (i >= n4) return;
    float4 v = w[i];
    ushort4 o;
    o.x = f16bits(v.x); o.y = f16bits(v.y); o.z = f16bits(v.z); o.w = f16bits(v.w);
    q[i] = o;
}

// ---------------- embedding (fp16 out) ----------------
__global__ void embed_kernel(const int* __restrict__ ids, const float* __restrict__ emb,
                             const float* __restrict__ pos, __half* __restrict__ e16) {
    int i = blockIdx.x * 256 + threadIdx.x;
    int d = i & (DD - 1);
    int s = (i >> 10) & (SS - 1);
    int b = i >> 19;
    int tok = ids[b * SS + s];
    float w = emb[(size_t)tok * DD + d];
    float tn = g_scale[0] * rintf(fminf(fmaxf(w * g_scaleinv[0], -1.f), 1.f));
    e16[i] = __float2half(tn + pos[s * DD + d]);
}

// ---------------- single-pass FP16 GEMM NT, 3-stage cp.async pipeline ----------------
// C[m,n] = [scale*] sum_k A16[m,k]*B16[n,k]  [+bias] [relu]
#define HG_STAGE 20480                 // A(10240) + B(10240) per stage
#define HG_SMEM (3 * HG_STAGE)         // 61440 B

template<bool RELU, bool OUT_F16, bool SCALED>
__global__ __launch_bounds__(256) void hgemm(
    const __half* __restrict__ A, const __half* __restrict__ B,
    float* __restrict__ C, __half* __restrict__ C16,
    const float* __restrict__ bias,
    int M, int N, int Kld, int kLen, int slot)
{
    extern __shared__ __align__(16) __half smh[];
    const int t = threadIdx.x;
    const int lane = t & 31;
    const int w = t >> 5;
    const int warpM = (w >> 1) << 5;
    const int warpN = (w & 1) << 6;
    const int bm = blockIdx.y << 7, bn = blockIdx.x << 7;
    const int kOff = blockIdx.z * kLen;
    if (gridDim.z > 1) C += (size_t)blockIdx.z * ((size_t)M * N);

    const __half* gA = A + (size_t)bm * Kld + kOff;
    const __half* gB = B + (size_t)bn * Kld + kOff;
    const unsigned uS = (unsigned)__cvta_generic_to_shared(smh);

    const int lrow = t >> 2;
    const int lcol = (t & 3) << 3;
    const unsigned wro = (unsigned)(lrow * 80 + lcol * 2);

    float acc[2][8][4];
#pragma unroll
    for (int i = 0; i < 2; i++)
#pragma unroll
        for (int j = 0; j < 8; j++)
#pragma unroll
            for (int p = 0; p < 4; p++) acc[i][j][p] = 0.f;

    const int NS = kLen >> 5;

#define HG_LOAD(s) do { \
    unsigned _b = uS + (unsigned)((s) % 3) * HG_STAGE; \
    int _k = (s) << 5; \
    CP16(_b + wro,                     gA + (size_t)lrow * Kld + _k + lcol); \
    CP16(_b + wro + 64 * 80,           gA + (size_t)(lrow + 64) * Kld + _k + lcol); \
    CP16(_b + 10240 + wro,             gB + (size_t)lrow * Kld + _k + lcol); \
    CP16(_b + 10240 + wro + 64 * 80,   gB + (size_t)(lrow + 64) * Kld + _k + lcol); \
    CPCOMMIT(); \
} while (0)

    HG_LOAD(0);
    if (NS > 1) HG_LOAD(1); else CPCOMMIT();

    for (int s = 0; s < NS; s++) {
        CPWAIT_1();
        __syncthreads();
        unsigned base = uS + (unsigned)(s % 3) * HG_STAGE;
#pragma unroll
        for (int kk = 0; kk < 32; kk += 16) {
            uint32_t af[2][4], bf[4][4];
#pragma unroll
            for (int mt = 0; mt < 2; mt++) {
                unsigned ra = base + (unsigned)((warpM + (mt << 4) + (lane & 15)) * 80 + ((kk + ((lane >> 4) << 3)) << 1));
                LDSM4(af[mt], ra);
            }
#pragma unroll
            for (int bj = 0; bj < 4; bj++) {
                unsigned rb = base + 10240u + (unsigned)((warpN + (bj << 4) + ((lane >> 4) << 3) + (lane & 7)) * 80 + ((kk + (((lane >> 3) & 1) << 3)) << 1));
                LDSM4(bf[bj], rb);
            }
#pragma unroll
            for (int mt = 0; mt < 2; mt++)
#pragma unroll
                for (int nt = 0; nt < 8; nt++) {
                    uint32_t b0 = bf[nt >> 1][(nt & 1) << 1];
                    uint32_t b1 = bf[nt >> 1][((nt & 1) << 1) + 1];
                    HMMA16816(acc[mt][nt], af[mt], b0, b1);
                }
        }
        if (s + 2 < NS) HG_LOAD(s + 2); else CPCOMMIT();
    }
#undef HG_LOAD

    const float sc = SCALED ? g_scale[slot] : 1.f;
#pragma unroll
    for (int mt = 0; mt < 2; mt++)
#pragma unroll
        for (int nt = 0; nt < 8; nt++) {
            int row = bm + warpM + (mt << 4) + (lane >> 2);
            int col = bn + warpN + (nt << 3) + ((lane & 3) << 1);
#pragma unroll
            for (int half = 0; half < 2; half++) {
                int r = row + half * 8;
                float v0 = acc[mt][nt][half * 2 + 0];
                float v1 = acc[mt][nt][half * 2 + 1];
                if (SCALED) { v0 *= sc; v1 *= sc; }
                if (bias) { v0 += bias[col]; v1 += bias[col + 1]; }
                if (RELU) { v0 = fmaxf(v0, 0.f); v1 = fmaxf(v1, 0.f); }
                if (OUT_F16) {
                    C16[(size_t)r * N + col]     = __float2half(v0);
                    C16[(size_t)r * N + col + 1] = __float2half(v1);
                } else {
                    C[(size_t)r * N + col]     = v0;
                    C[(size_t)r * N + col + 1] = v1;
                }
            }
        }
}

// ---------------- fused split-K reduce + residual + LayerNorm (+fp16 out) ----------------
__global__ void ln_red(const float* __restrict__ bias, float* __restrict__ x,
                       __half* __restrict__ o16,
                       const float* __restrict__ gamma, const float* __restrict__ beta)
{
    __shared__ float sred[256];
    const int row = blockIdx.x, t = threadIdx.x;
    const size_t off = (size_t)row * DD;
    float4 p0 = ((const float4*)(g_psum + off))[t];
    float4 p1 = ((const float4*)(g_psum + MMDD + off))[t];
    float4 p2 = ((const float4*)(g_psum + 2 * MMDD + off))[t];
    float4 p3 = ((const float4*)(g_psum + 3 * MMDD + off))[t];
    float4 bb = ((const float4*)bias)[t];
    float4 rr = ((const float4*)(x + off))[t];
    float4 v;
    v.x = ((p0.x + p1.x) + (p2.x + p3.x)) + bb.x + rr.x;
    v.y = ((p0.y + p1.y) + (p2.y + p3.y)) + bb.y + rr.y;
    v.z = ((p0.z + p1.z) + (p2.z + p3.z)) + bb.z + rr.z;
    v.w = ((p0.w + p1.w) + (p2.w + p3.w)) + bb.w + rr.w;

    sred[t] = v.x + v.y + v.z + v.w;
    __syncthreads();
#pragma unroll
    for (int o = 128; o > 0; o >>= 1) { if (t < o) sred[t] += sred[t + o]; __syncthreads(); }
    float mean = sred[0] * (1.f / 1024.f);
    __syncthreads();
    float dx = v.x - mean, dy = v.y - mean, dz = v.z - mean, dw = v.w - mean;
    sred[t] = dx * dx + dy * dy + dz * dz + dw * dw;
    __syncthreads();
#pragma unroll
    for (int o = 128; o > 0; o >>= 1) { if (t < o) sred[t] += sred[t + o]; __syncthreads(); }
    float rstd = rsqrtf(sred[0] * (1.f / 1024.f) + EPSLN);
    float4 g = ((const float4*)gamma)[t];
    float4 b = ((const float4*)beta)[t];
    float4 o4;
    o4.x = dx * rstd * g.x + b.x;
    o4.y = dy * rstd * g.y + b.y;
    o4.z = dz * rstd * g.z + b.z;
    o4.w = dw * rstd * g.w + b.w;
    ((float4*)(x + off))[t] = o4;
    ushort4 h;
    h.x = f16bits(o4.x); h.y = f16bits(o4.y); h.z = f16bits(o4.z); h.w = f16bits(o4.w);
    ((ushort4*)(o16 + off))[t] = h;
}

// ---------------- final LayerNorm (fp16 out) ----------------
__global__ void ln_final(const float* __restrict__ in, __half* __restrict__ o16,
                         const float* __restrict__ gamma, const float* __restrict__ beta)
{
    __shared__ float sred[256];
    const int row = blockIdx.x, t = threadIdx.x;
    const float4 v = ((const float4*)(in + (size_t)row * DD))[t];
    sred[t] = v.x + v.y + v.z + v.w;
    __syncthreads();
#pragma unroll
    for (int o = 128; o > 0; o >>= 1) { if (t < o) sred[t] += sred[t + o]; __syncthreads(); }
    float mean = sred[0] * (1.f / 1024.f);
    __syncthreads();
    float dx = v.x - mean, dy = v.y - mean, dz = v.z - mean, dw = v.w - mean;
    sred[t] = dx * dx + dy * dy + dz * dz + dw * dw;
    __syncthreads();
#pragma unroll
    for (int o = 128; o > 0; o >>= 1) { if (t < o) sred[t] += sred[t + o]; __syncthreads(); }
    float rstd = rsqrtf(sred[0] * (1.f / 1024.f) + EPSLN);
    float4 g = ((const float4*)gamma)[t];
    float4 b = ((const float4*)beta)[t];
    ushort4 h;
    h.x = f16bits(dx * rstd * g.x + b.x);
    h.y = f16bits(dy * rstd * g.y + b.y);
    h.z = f16bits(dz * rstd * g.z + b.z);
    h.w = f16bits(dw * rstd * g.w + b.w);
    ((ushort4*)(o16 + (size_t)row * DD))[t] = h;
}

// ---------------- flag-array grid barrier ----------------
__device__ __forceinline__ void gbarf(unsigned k) {
    __syncthreads();
    if (threadIdx.x == 0) {
        __threadfence();
        g_flags[(unsigned)blockIdx.x * 32] = k;
    }
    if (threadIdx.x < GRU_CTAS) {
        while (g_flags[(unsigned)threadIdx.x * 32] < k) { }
    }
    __syncthreads();
}

// ---------------- persistent GRU ----------------
__global__ __launch_bounds__(192, 1) void gru_kernel(
    const float* __restrict__ gi, const float* __restrict__ whh,
    const float* __restrict__ bhh, float* __restrict__ x,
    __half* __restrict__ x16)
{
    __shared__ float hs[2048];
    __shared__ float sgh[48];
    __shared__ float sbh[24];
    const int tid = threadIdx.x;
    const int base = blockIdx.x * 8;
    const int r = tid >> 3, j = tid & 7;
    const int gg = r >> 3, ddim = r & 7;

    float4 wreg[32];
    const float* wrow = whh + (size_t)(gg * 1024 + base + ddim) * 1024;
#pragma unroll
    for (int i = 0; i < 32; i++)
        wreg[i] = *(const float4*)(wrow + (i * 8 + j) * 4);

    if (tid < 24) sbh[tid] = bhh[(tid >> 3) * 1024 + base + (tid & 7)];
    if (tid < 16) {
        int b = tid & 1, d0 = base + (tid >> 1);
        g_h[0][2 * d0 + b] = 0.f;
    }
    gbarf(1);

    for (int s = 0; s < SS; s++) {
        const int rb = s & 1, wb = rb ^ 1;

        float ir = 0.f, iz = 0.f, inn = 0.f;
        if (tid < 16) {
            int b = tid & 1, d0 = tid >> 1;
            int dg = base + d0;
            const float* gim = gi + ((size_t)b * SS + s) * 3072;
            ir  = __ldcg(gim + dg);
            iz  = __ldcg(gim + 1024 + dg);
            inn = __ldcg(gim + 2048 + dg);
        }

        for (int idx = tid; idx < 512; idx += 192)
            ((float4*)hs)[idx] = __ldcg((const float4*)&g_h[rb][0] + idx);
        __syncthreads();

        unsigned long long ac0 = 0ull, ac1 = 0ull, ac2 = 0ull, ac3 = 0ull;
#pragma unroll
        for (int i = 0; i < 32; i++) {
            int c4 = i * 8 + j;
            float4 hA = ((const float4*)hs)[c4 * 2];
            float4 hB = ((const float4*)hs)[c4 * 2 + 1];
            float4 w = wreg[i];
            ffma2(ac0, pk2(w.x, w.x), pk2(hA.x, hA.y));
            ffma2(ac1, pk2(w.y, w.y), pk2(hA.z, hA.w));
            ffma2(ac2, pk2(w.z, w.z), pk2(hB.x, hB.y));
            ffma2(ac3, pk2(w.w, w.w), pk2(hB.z, hB.w));
        }
        float2 s0 = unpk(ac0), s1 = unpk(ac1), s2 = unpk(ac2), s3 = unpk(ac3);
        float acc0 = (s0.x + s1.x) + (s2.x + s3.x);
        float acc1 = (s0.y + s1.y) + (s2.y + s3.y);
#pragma unroll
        for (int o = 4; o; o >>= 1) {
            acc0 += __shfl_down_sync(0xffffffffu, acc0, o);
            acc1 += __shfl_down_sync(0xffffffffu, acc1, o);
        }
        if (j == 0) { sgh[r * 2] = acc0 + sbh[r]; sgh[r * 2 + 1] = acc1 + sbh[r]; }
        __syncthreads();

        if (tid < 16) {
            int b = tid & 1, d0 = tid >> 1;
            int dg = base + d0;
            float hr = sgh[d0 * 2 + b], hz = sgh[(8 + d0) * 2 + b], hn = sgh[(16 + d0) * 2 + b];
            float rg = 1.f / (1.f + expf(-(ir + hr)));
            float zg = 1.f / (1.f + expf(-(iz + hz)));
            float ng = tanhf(inn + rg * hn);
            float hp = hs[2 * dg + b];
            float hv = (1.f - zg) * ng + zg * hp;
            __stcg(&g_h[wb][2 * dg + b], hv);
            size_t m = (size_t)b * SS + s;
            x[m * 1024 + dg] = hv;
            x16[m * 1024 + dg] = __float2half(hv);
        }
        if (s + 1 < SS) gbarf(2 + s);
    }

    if (tid == 0) {
        __threadfence();
        unsigned a = atomicAdd(&g_ack, 1u);
        if (a == GRU_CTAS - 1) {
            for (int i = 0; i < GRU_CTAS; i++) g_flags[i * 32] = 0;
            __threadfence();
            g_ack = 0;
            __threadfence();
        }
    }
}

// ---------------- launch ----------------
extern "C" void kernel_launch(void* const* d_in, const int* in_sizes, int n_in,
                              void* d_out, int out_size) {
    const int*   ids     = (const int*)  d_in[0];
    const float* emb     = (const float*)d_in[1];
    const float* pos     = (const float*)d_in[2];
    const float* gru_wih = (const float*)d_in[3];
    const float* gru_whh = (const float*)d_in[4];
    const float* gru_bih = (const float*)d_in[5];
    const float* gru_bhh = (const float*)d_in[6];
    const float* syn_w   = (const float*)d_in[7];
    const float* syn_b   = (const float*)d_in[8];
    const float* out_w   = (const float*)d_in[9];
    const float* out_b   = (const float*)d_in[10];
    const float* ln_g    = (const float*)d_in[11];
    const float* ln_b    = (const float*)d_in[12];
    const float* on_g    = (const float*)d_in[13];
    const float* on_b    = (const float*)d_in[14];
    const float* head_w  = (const float*)d_in[15];
    const float* head_b  = (const float*)d_in[16];
    float* logits = (float*)d_out;

    float *xg, *gig, *psg;
    __half *w16ih, *q16syn, *q16out, *q16head, *x16, *h16, *y16;
    cudaGetSymbolAddress((void**)&xg,   g_x);
    cudaGetSymbolAddress((void**)&gig,  g_gi);
    cudaGetSymbolAddress((void**)&psg,  g_psum);
    cudaGetSymbolAddress((void**)&w16ih,  g_w16ih);
    cudaGetSymbolAddress((void**)&q16syn,  g_q16syn);
    cudaGetSymbolAddress((void**)&q16out,  g_q16out);
    cudaGetSymbolAddress((void**)&q16head, g_q16head);
    cudaGetSymbolAddress((void**)&x16, g_x16);
    cudaGetSymbolAddress((void**)&h16, g_h16);
    cudaGetSymbolAddress((void**)&y16, g_y16);

    static cudaStream_t s1, s2;
    static cudaEvent_t evRoot, ev1, ev2;
    static bool init_done = false;
    if (!init_done) {
        cudaFuncSetAttribute(hgemm<true,  true,  true >, cudaFuncAttributeMaxDynamicSharedMemorySize, HG_SMEM);
        cudaFuncSetAttribute(hgemm<false, false, true >, cudaFuncAttributeMaxDynamicSharedMemorySize, HG_SMEM);
        cudaFuncSetAttribute(hgemm<false, false, false>, cudaFuncAttributeMaxDynamicSharedMemorySize, HG_SMEM);
        cudaStreamCreateWithFlags(&s1, cudaStreamNonBlocking);
        cudaStreamCreateWithFlags(&s2, cudaStreamNonBlocking);
        cudaEventCreateWithFlags(&evRoot, cudaEventDisableTiming);
        cudaEventCreateWithFlags(&ev1, cudaEventDisableTiming);
        cudaEventCreateWithFlags(&ev2, cudaEventDisableTiming);
        init_done = true;
    }

    long nVD4 = (long)VV * DD / 4, nND4 = (long)NNH * DD / 4;
    int n4wih = 3 * DD * DD / 4;

    cudaEventRecord(evRoot, 0);
    cudaStreamWaitEvent(s1, evRoot, 0);
    cudaStreamWaitEvent(s2, evRoot, 0);

    // main stream: wih cvt -> emb scale -> embed -> in-proj (fp16) -> GRU
    f16cvt<<<n4wih / 256, 256>>>((const float4*)gru_wih, (ushort4*)w16ih, n4wih);
    absmean_part<<<512, 256>>>((const float4*)emb, nVD4, 0);
    absmean_final<<<1, 256>>>(0);
    embed_kernel<<<4096, 256>>>(ids, emb, pos, y16);
    hgemm<false, false, false><<<dim3(3072 / 128, MROWS / 128, 1), 256, HG_SMEM>>>(
        y16, w16ih, gig, (__half*)0, gru_bih, MROWS, 3072, DD, DD, 0);
    gru_kernel<<<GRU_CTAS, 192>>>(gig, gru_whh, gru_bhh, xg, x16);

    // side stream 1: layer weight scales + fp16 quantization
    for (int l = 0; l < 4; l++) {
        absmean_part<<<512, 256, 0, s1>>>((const float4*)(syn_w + (size_t)l * NNH * DD), nND4, 2 + l);
        absmean_part<<<512, 256, 0, s1>>>((const float4*)(out_w + (size_t)l * DD * NNH), nND4, 6 + l);
    }
    absmean_final<<<8, 256, 0, s1>>>(2);
    for (int l = 0; l < 4; l++) {
        tern_quant16<<<(int)(nND4 / 256), 256, 0, s1>>>((const float4*)(syn_w + (size_t)l * NNH * DD),
                                                        (ushort4*)(q16syn + (size_t)l * NNH * DD), 2 + l, (int)nND4);
        tern_quant16<<<(int)(nND4 / 256), 256, 0, s1>>>((const float4*)(out_w + (size_t)l * DD * NNH),
                                                        (ushort4*)(q16out + (size_t)l * DD * NNH), 6 + l, (int)nND4);
    }
    cudaEventRecord(ev1, s1);

    // side stream 2: head scale + fp16 quantization
    absmean_part<<<512, 256, 0, s2>>>((const float4*)head_w, nVD4, 1);
    absmean_final<<<1, 256, 0, s2>>>(1);
    tern_quant16<<<(int)(nVD4 / 256), 256, 0, s2>>>((const float4*)head_w, (ushort4*)q16head, 1, (int)nVD4);
    cudaEventRecord(ev2, s2);

    // join layer-weight stream, MLP (single-pass fp16, 3-stage)
    cudaStreamWaitEvent(0, ev1, 0);
    for (int l = 0; l < 4; l++) {
        hgemm<true, true, true><<<dim3(NNH / 128, MROWS / 128, 1), 256, HG_SMEM>>>(
            x16, q16syn + (size_t)l * NNH * DD, (float*)0, h16,
            syn_b + (size_t)l * NNH, MROWS, NNH, DD, DD, 2 + l);
        hgemm<false, false, true><<<dim3(DD / 128, MROWS / 128, 4), 256, HG_SMEM>>>(
            h16, q16out + (size_t)l * DD * NNH, psg, (__half*)0,
            (const float*)0, MROWS, DD, NNH, NNH / 4, 6 + l);
        ln_red<<<MROWS, 256>>>(out_b + (size_t)l * DD, xg, x16,
                               ln_g + (size_t)l * DD, ln_b + (size_t)l * DD);
    }

    // join head stream, final LN + head
    cudaStreamWaitEvent(0, ev2, 0);
    ln_final<<<MROWS, 256>>>(xg, y16, on_g, on_b);
    hgemm<false, false, true><<<dim3(VV / 128, MROWS / 128, 1), 256, HG_SMEM>>>(
        y16, q16head, logits, (__half*)0, head_b, MROWS, VV, DD, DD, 1);
}